// round 8
// baseline (speedup 1.0000x reference)
#include <cuda_runtime.h>
#include <cuda_bf16.h>
#include <cooperative_groups.h>
#include <cstdint>
#include <cstddef>

namespace cg = cooperative_groups;

// Problem dims
#define Vv 32000
#define Ee 300
#define Hh 300
#define G4 1200   // 4*H
#define Bb 128
#define Tt 512
#define Oo 9

// ---------------- scratch (device globals: allocation-free rule) ----------------
__device__ float g_proj[2ull * Vv * G4];          // 307.2 MB
__device__ float g_h[2ull * Bb * Tt * Hh];        // 157.3 MB

// ---------------- packed fp32x2 helpers (sm_100+ FFMA2) ----------------
typedef unsigned long long ull_t;

__device__ __forceinline__ void ffma2(ull_t& d, ull_t a, ull_t b) {
    asm("fma.rn.f32x2 %0, %1, %2, %0;" : "+l"(d) : "l"(a), "l"(b));
}
union F4U { float4 f; ull_t u[2]; };
union U2F { ull_t u; float2 f; };

// ---------------- mbarrier / cluster helpers ----------------
__device__ __forceinline__ void mbar_init(uint32_t addr, uint32_t count) {
    asm volatile("mbarrier.init.shared.b64 [%0], %1;" :: "r"(addr), "r"(count) : "memory");
}
__device__ __forceinline__ uint32_t mapa_u32(uint32_t addr, uint32_t rank) {
    uint32_t r;
    asm("mapa.shared::cluster.u32 %0, %1, %2;" : "=r"(r) : "r"(addr), "r"(rank));
    return r;
}
__device__ __forceinline__ void mbar_arrive_remote(uint32_t local_addr, uint32_t rank) {
    uint32_t ra = mapa_u32(local_addr, rank);
    asm volatile("mbarrier.arrive.shared::cluster.b64 _, [%0];" :: "r"(ra) : "memory");
}
__device__ __forceinline__ void mbar_expect_tx(uint32_t addr, uint32_t bytes) {
    asm volatile("mbarrier.arrive.expect_tx.shared.b64 _, [%0], %1;"
                 :: "r"(addr), "r"(bytes) : "memory");
}
// acquire.cta parity wait (NO cluster-scope acquire -> no CCTL.IVALL)
__device__ __forceinline__ void mbar_wait_parity(uint32_t addr, uint32_t parity) {
    uint32_t done;
    asm volatile(
        "{\n\t"
        ".reg .pred p;\n\t"
        "mbarrier.try_wait.parity.acquire.cta.shared::cta.b64 p, [%1], %2;\n\t"
        "selp.b32 %0, 1, 0, p;\n\t"
        "}"
        : "=r"(done) : "r"(addr), "r"(parity) : "memory");
    while (!done) {
        asm volatile(
            "{\n\t"
            ".reg .pred p;\n\t"
            "mbarrier.try_wait.parity.acquire.cta.shared::cta.b64 p, [%1], %2, 0x989680;\n\t"
            "selp.b32 %0, 1, 0, p;\n\t"
            "}"
            : "=r"(done) : "r"(addr), "r"(parity) : "memory");
    }
}
// async remote store, completes on REMOTE mbarrier (tx bytes)
__device__ __forceinline__ void st_async_b64(uint32_t raddr, ull_t v, uint32_t rmbar) {
    asm volatile("st.async.shared::cluster.mbarrier::complete_tx::bytes.b64 [%0], %1, [%2];"
                 :: "r"(raddr), "l"(v), "r"(rmbar) : "memory");
}

// =================================================================
// K1: vocab projection GEMM  (known-good R2 version)
// =================================================================
#define K1_BM 128
#define K1_BN 64
#define K1_BK 16

__global__ void proj_kernel(const float* __restrict__ emb,
                            const float* __restrict__ Wf,
                            const float* __restrict__ Wb,
                            const float* __restrict__ bf,
                            const float* __restrict__ bb) {
    __shared__ float As[K1_BK][K1_BM + 4];
    __shared__ float Bs[K1_BK][K1_BN + 4];

    const int dir = blockIdx.z;
    const float* __restrict__ W    = dir ? Wb : Wf;
    const float* __restrict__ bias = dir ? bb : bf;
    const int n0 = blockIdx.x * K1_BN;
    const int m0 = blockIdx.y * K1_BM;
    const int tid = threadIdx.x;
    const int tx = tid & 15;
    const int ty = tid >> 4;

    float acc[8][4];
#pragma unroll
    for (int i = 0; i < 8; i++)
#pragma unroll
        for (int j = 0; j < 4; j++) acc[i][j] = 0.f;

    for (int kk = 0; kk < Ee; kk += K1_BK) {
#pragma unroll
        for (int it = 0; it < 2; it++) {
            int f = tid + it * 256;
            int row = f >> 2;
            int kq  = (f & 3) * 4;
            int k0  = kk + kq;
            const float* src = emb + (size_t)(m0 + row) * Ee;
            float4 v;
            if (k0 + 3 < Ee) {
                v = *(const float4*)(src + k0);
            } else {
                v.x = (k0 + 0 < Ee) ? src[k0 + 0] : 0.f;
                v.y = (k0 + 1 < Ee) ? src[k0 + 1] : 0.f;
                v.z = (k0 + 2 < Ee) ? src[k0 + 2] : 0.f;
                v.w = (k0 + 3 < Ee) ? src[k0 + 3] : 0.f;
            }
            As[kq + 0][row] = v.x; As[kq + 1][row] = v.y;
            As[kq + 2][row] = v.z; As[kq + 3][row] = v.w;
        }
        {
            int f = tid;
            int row = f >> 2;
            int kq  = (f & 3) * 4;
            int k0  = kk + kq;
            int n   = n0 + row;
            float4 v = make_float4(0.f, 0.f, 0.f, 0.f);
            if (n < G4) {
                const float* src = W + (size_t)n * Ee;
                if (k0 + 3 < Ee) {
                    v = *(const float4*)(src + k0);
                } else {
                    v.x = (k0 + 0 < Ee) ? src[k0 + 0] : 0.f;
                    v.y = (k0 + 1 < Ee) ? src[k0 + 1] : 0.f;
                    v.z = (k0 + 2 < Ee) ? src[k0 + 2] : 0.f;
                    v.w = (k0 + 3 < Ee) ? src[k0 + 3] : 0.f;
                }
            }
            Bs[kq + 0][row] = v.x; Bs[kq + 1][row] = v.y;
            Bs[kq + 2][row] = v.z; Bs[kq + 3][row] = v.w;
        }
        __syncthreads();

#pragma unroll
        for (int k = 0; k < K1_BK; k++) {
            float4 a0 = *(float4*)&As[k][ty * 8];
            float4 a1 = *(float4*)&As[k][ty * 8 + 4];
            float4 bv = *(float4*)&Bs[k][tx * 4];
            float av[8] = {a0.x, a0.y, a0.z, a0.w, a1.x, a1.y, a1.z, a1.w};
            float bvv[4] = {bv.x, bv.y, bv.z, bv.w};
#pragma unroll
            for (int i = 0; i < 8; i++)
#pragma unroll
                for (int j = 0; j < 4; j++) acc[i][j] += av[i] * bvv[j];
        }
        __syncthreads();
    }

    float* cbase = g_proj + (size_t)dir * Vv * G4;
#pragma unroll
    for (int i = 0; i < 8; i++) {
        int m = m0 + ty * 8 + i;
#pragma unroll
        for (int j = 0; j < 4; j++) {
            int n = n0 + tx * 4 + j;
            if (n < G4) cbase[(size_t)m * G4 + n] = acc[i][j] + bias[n];
        }
    }
}

// =================================================================
// K2: BiLSTM recurrence. Cluster of 8 CTAs = (dir, 16 batch rows).
// CTA rank r owns hidden slice [r*40, r*40+40).
// SMEM: W_s2[k2][gi][2] (192 KB) + hbuf[2][k2][r][2] (2 x 19.2 KB)
// Sync: per-buffer full mbarrier (st.async complete_tx from 7 peers,
// expect_tx by owner) + per-buffer empty mbarrier (read-done, 8 arrives).
// NO cluster-scope fences in the loop (no CCTL.IVALL).
// Thread map (broadcast-friendly): warp covers 8 j x 4 rowgroups.
// =================================================================
#define REC_THREADS 160
#define W2_WORDS (150 * 320)               // 48000
#define HB_WORDS (150 * 32)                // 4800 per buffer
#define REC_SMEM ((W2_WORDS + 2 * HB_WORDS) * 4)   // 230400 B
#define H_TOTAL_BYTES 19200                // 300 cols x 16 rows x 4B

__device__ __forceinline__ float sigmoidf_(float x) {
    return 1.0f / (1.0f + __expf(-x));
}
__device__ __forceinline__ float tanhf_(float x) {
    float xx = fminf(fmaxf(x, -15.f), 15.f);
    float e = __expf(-2.0f * xx);
    return (1.0f - e) / (1.0f + e);
}

__global__ void __cluster_dims__(8, 1, 1) __launch_bounds__(REC_THREADS, 1)
lstm_rec_kernel(const int* __restrict__ x,
                const float* __restrict__ Whh_f,
                const float* __restrict__ Whh_b) {
    extern __shared__ float sm[];
    float* W_s2 = sm;                         // [k2][gi][2]
    float* hbuf0 = sm + W2_WORDS;             // [k2][r][2]
    float* hbuf1 = sm + W2_WORDS + HB_WORDS;  // [k2][r][2]
    __shared__ unsigned long long mbar_full[2];
    __shared__ unsigned long long mbar_empty[2];

    cg::cluster_group cluster = cg::this_cluster();

    const int bx   = blockIdx.x;
    const int cid  = bx >> 3;           // 0..15
    const int rank = bx & 7;            // 0..7
    const int dir  = cid >> 3;          // 0,1
    const int bg   = cid & 7;           // 0..7
    const int b0   = bg * 16;
    const int h0   = rank * 40;
    const int tid  = threadIdx.x;
    // broadcast-friendly map: warp = 8 j x 4 rowgroups
    const int j    = ((tid >> 5) << 3) + (tid & 7);   // 0..39
    const int rg   = (tid >> 3) & 3;                  // 0..3
    const bool validh = (h0 + j) < Hh;
    const int hjc = validh ? (h0 + j) : (Hh - 1);

    const float* __restrict__ Whh = dir ? Whh_b : Whh_f;

    const uint32_t full_a[2]  = { (uint32_t)__cvta_generic_to_shared(&mbar_full[0]),
                                  (uint32_t)__cvta_generic_to_shared(&mbar_full[1]) };
    const uint32_t empty_a[2] = { (uint32_t)__cvta_generic_to_shared(&mbar_empty[0]),
                                  (uint32_t)__cvta_generic_to_shared(&mbar_empty[1]) };
    const uint32_t hbuf_a[2]  = { (uint32_t)__cvta_generic_to_shared(hbuf0),
                                  (uint32_t)__cvta_generic_to_shared(hbuf1) };

    const int slice_words = (rank == 7) ? 320 : 640;
    const uint32_t own_bytes = (uint32_t)slice_words * 4u;
    const uint32_t expect_bytes = H_TOTAL_BYTES - own_bytes;

    // ---- init barriers ----
    if (tid == 0) {
        mbar_init(full_a[0], 1);  mbar_init(full_a[1], 1);
        mbar_init(empty_a[0], 8); mbar_init(empty_a[1], 8);
    }

    // ---- load weight slice into SMEM, k-pair interleaved ----
    {
        int gi = tid;                    // 0..159
        int g  = gi / 40;
        int jj = gi % 40;
        bool v = (h0 + jj) < Hh;
        const float* wrow = Whh + (size_t)(g * Hh + (v ? (h0 + jj) : 0)) * Hh;
        for (int k4 = 0; k4 < Hh; k4 += 4) {
            float4 w = v ? *(const float4*)(wrow + k4) : make_float4(0.f, 0.f, 0.f, 0.f);
            int k2 = k4 >> 1;
            *(float2*)(W_s2 + (k2 + 0) * 320 + gi * 2) = make_float2(w.x, w.y);
            *(float2*)(W_s2 + (k2 + 1) * 320 + gi * 2) = make_float2(w.z, w.w);
        }
    }
    // ---- zero h buffers ----
    for (int i = tid; i < 2 * HB_WORDS; i += REC_THREADS) hbuf0[i] = 0.f;
    __syncthreads();
    // barriers + zeroed buffers ready before any remote op
    cluster.sync();
    // pre-arm empty[1]: buffer 1 has never been read; first overwrite is step 0
    if (tid == 0) {
#pragma unroll
        for (int rr = 0; rr < 8; rr++) mbar_arrive_remote(empty_a[1], (uint32_t)rr);
    }

    const int* xr0 = x + (size_t)(b0 + rg * 4 + 0) * Tt;
    const int* xr1 = x + (size_t)(b0 + rg * 4 + 1) * Tt;
    const int* xr2 = x + (size_t)(b0 + rg * 4 + 2) * Tt;
    const int* xr3 = x + (size_t)(b0 + rg * 4 + 3) * Tt;
    const float* ptab = g_proj + (size_t)dir * Vv * G4;

    float c0 = 0.f, c1 = 0.f, c2 = 0.f, c3 = 0.f;

    const float* wb0 = W_s2 + (0 * 40 + j) * 2;
    const float* wb1 = W_s2 + (1 * 40 + j) * 2;
    const float* wb2 = W_s2 + (2 * 40 + j) * 2;
    const float* wb3 = W_s2 + (3 * 40 + j) * 2;
    const unsigned hb_off = (unsigned)(rg * 4) * 2;

    // staging word offset (within a buffer) for own h values
    const unsigned stage_base = ((unsigned)(h0 + j) >> 1) * 32 + ((unsigned)(h0 + j) & 1);
    // push mapping: own slice = contiguous words [h0*16, h0*16 + slice_words)
    const unsigned push_word = (unsigned)(h0 * 16) + (unsigned)tid * 4;
    const bool do_push = (tid * 4) < slice_words;
    const uint32_t push_byte = push_word * 4u;

    uint32_t fpar[2] = {0u, 0u};
    uint32_t epar[2] = {0u, 0u};

    // ---- prologue: gather xp for step 0 ----
    float xp[16];
    {
        const int t0 = dir ? (Tt - 1) : 0;
        const float* p0 = ptab + (size_t)xr0[t0] * G4 + hjc;
        const float* p1 = ptab + (size_t)xr1[t0] * G4 + hjc;
        const float* p2 = ptab + (size_t)xr2[t0] * G4 + hjc;
        const float* p3 = ptab + (size_t)xr3[t0] * G4 + hjc;
#pragma unroll
        for (int g = 0; g < 4; g++) {
            xp[0 * 4 + g] = p0[g * Hh];
            xp[1 * 4 + g] = p1[g * Hh];
            xp[2 * 4 + g] = p2[g * Hh];
            xp[3 * 4 + g] = p3[g * Hh];
        }
    }

    for (int ti = 0; ti < Tt; ti++) {
        const int tcur = dir ? (Tt - 1 - ti) : ti;
        const int buf  = ti & 1;
        const int nbuf = buf ^ 1;
        float* hcur  = buf ? hbuf1 : hbuf0;
        float* hnext = buf ? hbuf0 : hbuf1;

        // ---- prefetch next step's xp (issued before the wait; hidden) ----
        float xpn[16];
        {
            const int tin = (ti + 1 < Tt) ? (ti + 1) : ti;
            const int tn  = dir ? (Tt - 1 - tin) : tin;
            const float* p0 = ptab + (size_t)xr0[tn] * G4 + hjc;
            const float* p1 = ptab + (size_t)xr1[tn] * G4 + hjc;
            const float* p2 = ptab + (size_t)xr2[tn] * G4 + hjc;
            const float* p3 = ptab + (size_t)xr3[tn] * G4 + hjc;
#pragma unroll
            for (int g = 0; g < 4; g++) {
                xpn[0 * 4 + g] = p0[g * Hh];
                xpn[1 * 4 + g] = p1[g * Hh];
                xpn[2 * 4 + g] = p2[g * Hh];
                xpn[3 * 4 + g] = p3[g * Hh];
            }
        }

        // ---- wait: h of step ti fully delivered (7 peers' st.async + own stage) ----
        if (ti > 0) {
            mbar_wait_parity(full_a[buf], fpar[buf]);
            fpar[buf] ^= 1u;
        }

        // ---- gate dots: acc2[r][g], f32x2 paired over (k even, k odd) ----
        const float* hb = hcur + hb_off;
        ull_t acc2[4][4];
#pragma unroll
        for (int r = 0; r < 4; r++)
#pragma unroll
            for (int g = 0; g < 4; g++) acc2[r][g] = 0ull;

#pragma unroll 5
        for (int k2 = 0; k2 < 150; k2++) {
            ull_t wv0 = *(const ull_t*)(wb0 + k2 * 320);
            ull_t wv1 = *(const ull_t*)(wb1 + k2 * 320);
            ull_t wv2 = *(const ull_t*)(wb2 + k2 * 320);
            ull_t wv3 = *(const ull_t*)(wb3 + k2 * 320);
            F4U h01, h23;
            h01.f = *(const float4*)(hb + k2 * 32);
            h23.f = *(const float4*)(hb + k2 * 32 + 4);
            ffma2(acc2[0][0], h01.u[0], wv0); ffma2(acc2[0][1], h01.u[0], wv1);
            ffma2(acc2[0][2], h01.u[0], wv2); ffma2(acc2[0][3], h01.u[0], wv3);
            ffma2(acc2[1][0], h01.u[1], wv0); ffma2(acc2[1][1], h01.u[1], wv1);
            ffma2(acc2[1][2], h01.u[1], wv2); ffma2(acc2[1][3], h01.u[1], wv3);
            ffma2(acc2[2][0], h23.u[0], wv0); ffma2(acc2[2][1], h23.u[0], wv1);
            ffma2(acc2[2][2], h23.u[0], wv2); ffma2(acc2[2][3], h23.u[0], wv3);
            ffma2(acc2[3][0], h23.u[1], wv0); ffma2(acc2[3][1], h23.u[1], wv1);
            ffma2(acc2[3][2], h23.u[1], wv2); ffma2(acc2[3][3], h23.u[1], wv3);
        }

        float acc[16];
#pragma unroll
        for (int r = 0; r < 4; r++)
#pragma unroll
            for (int g = 0; g < 4; g++) {
                U2F v; v.u = acc2[r][g];
                acc[r * 4 + g] = v.f.x + v.f.y;
            }

        // ---- LSTM cell update (c in registers) ----
        float hn[4];
        {
            float gi_, gf_, gg_, go_, tg;
            gi_ = acc[0] + xp[0];  gf_ = acc[1] + xp[1];  gg_ = acc[2] + xp[2];  go_ = acc[3] + xp[3];
            tg = tanhf_(gg_); c0 = sigmoidf_(gf_) * c0 + sigmoidf_(gi_) * tg; hn[0] = sigmoidf_(go_) * tanhf_(c0);
            gi_ = acc[4] + xp[4];  gf_ = acc[5] + xp[5];  gg_ = acc[6] + xp[6];  go_ = acc[7] + xp[7];
            tg = tanhf_(gg_); c1 = sigmoidf_(gf_) * c1 + sigmoidf_(gi_) * tg; hn[1] = sigmoidf_(go_) * tanhf_(c1);
            gi_ = acc[8] + xp[8];  gf_ = acc[9] + xp[9];  gg_ = acc[10] + xp[10]; go_ = acc[11] + xp[11];
            tg = tanhf_(gg_); c2 = sigmoidf_(gf_) * c2 + sigmoidf_(gi_) * tg; hn[2] = sigmoidf_(go_) * tanhf_(c2);
            gi_ = acc[12] + xp[12]; gf_ = acc[13] + xp[13]; gg_ = acc[14] + xp[14]; go_ = acc[15] + xp[15];
            tg = tanhf_(gg_); c3 = sigmoidf_(gf_) * c3 + sigmoidf_(gi_) * tg; hn[3] = sigmoidf_(go_) * tanhf_(c3);
        }

        if (ti + 1 < Tt) {
            // ---- stage new h into NEXT buffer's own slice (local STS) ----
            if (validh) {
                hnext[stage_base + (rg * 4 + 0) * 2] = hn[0];
                hnext[stage_base + (rg * 4 + 1) * 2] = hn[1];
                hnext[stage_base + (rg * 4 + 2) * 2] = hn[2];
                hnext[stage_base + (rg * 4 + 3) * 2] = hn[3];
            }
            __syncthreads();   // reads of hcur done CTA-wide + staging visible

            // signal: this CTA finished reading buffer `buf` (reusable at ti+2)
            if (tid == 0) {
#pragma unroll
                for (int rr = 0; rr < 8; rr++) mbar_arrive_remote(empty_a[buf], (uint32_t)rr);
            }

            // wait: all CTAs done reading buffer `nbuf` (its step ti-1 data)
            mbar_wait_parity(empty_a[nbuf], epar[nbuf]);
            epar[nbuf] ^= 1u;

            // ---- push own slice to 7 peers via st.async (completes on their full[nbuf]) ----
            if (do_push) {
                F4U v;
                v.f = *(const float4*)(hnext + push_word);
#pragma unroll
                for (int rr = 0; rr < 8; rr++) {
                    if (rr == rank) continue;
                    uint32_t raddr = mapa_u32(hbuf_a[nbuf] + push_byte, (uint32_t)rr);
                    uint32_t rmbar = mapa_u32(full_a[nbuf], (uint32_t)rr);
                    st_async_b64(raddr, v.u[0], rmbar);
                    st_async_b64(raddr + 8, v.u[1], rmbar);
                }
            }
            // arm own full[nbuf]: expect 7 peers' slice bytes
            if (tid == 0) mbar_expect_tx(full_a[nbuf], expect_bytes);
        }

        // ---- write h to global for the output stage ----
        if (validh) {
            size_t base = ((size_t)(dir * Bb + b0 + rg * 4) * Tt + tcur) * Hh + (h0 + j);
            const size_t strideB = (size_t)Tt * Hh;
            g_h[base + 0 * strideB] = hn[0];
            g_h[base + 1 * strideB] = hn[1];
            g_h[base + 2 * strideB] = hn[2];
            g_h[base + 3 * strideB] = hn[3];
        }

        xp[0]=xpn[0]; xp[1]=xpn[1]; xp[2]=xpn[2]; xp[3]=xpn[3];
        xp[4]=xpn[4]; xp[5]=xpn[5]; xp[6]=xpn[6]; xp[7]=xpn[7];
        xp[8]=xpn[8]; xp[9]=xpn[9]; xp[10]=xpn[10]; xp[11]=xpn[11];
        xp[12]=xpn[12]; xp[13]=xpn[13]; xp[14]=xpn[14]; xp[15]=xpn[15];
    }
    // drain: ensure no CTA exits while peers may still st.async into it
    cluster.sync();
}

// =================================================================
// K3: output linear + softmax. One warp per (b,t).
// =================================================================
__global__ void out_kernel(const float* __restrict__ W_lin,
                           const float* __restrict__ b_lin,
                           float* __restrict__ out) {
    const int warp = (blockIdx.x * blockDim.x + threadIdx.x) >> 5;
    const int lane = threadIdx.x & 31;
    if (warp >= Bb * Tt) return;
    const int b = warp / Tt;
    const int t = warp % Tt;

    const float* hf = g_h + ((size_t)(0 * Bb + b) * Tt + t) * Hh;
    const float* hb = g_h + ((size_t)(1 * Bb + b) * Tt + t) * Hh;

    float acc[Oo];
#pragma unroll
    for (int o = 0; o < Oo; o++) acc[o] = 0.f;

    for (int k = lane; k < Hh; k += 32) {
        float a = hf[k];
        float c = hb[k];
#pragma unroll
        for (int o = 0; o < Oo; o++)
            acc[o] += a * W_lin[o * (2 * Hh) + k] + c * W_lin[o * (2 * Hh) + Hh + k];
    }
#pragma unroll
    for (int o = 0; o < Oo; o++) {
#pragma unroll
        for (int off = 16; off > 0; off >>= 1)
            acc[o] += __shfl_xor_sync(0xFFFFFFFFu, acc[o], off);
        acc[o] += b_lin[o];
    }
    float mx = acc[0];
#pragma unroll
    for (int o = 1; o < Oo; o++) mx = fmaxf(mx, acc[o]);
    float s = 0.f;
    float e[Oo];
#pragma unroll
    for (int o = 0; o < Oo; o++) { e[o] = __expf(acc[o] - mx); s += e[o]; }
    float inv = 1.0f / s;
    if (lane < Oo) out[(size_t)warp * Oo + lane] = e[lane] * inv;
}

// =================================================================
// launcher
// =================================================================
extern "C" void kernel_launch(void* const* d_in, const int* in_sizes, int n_in,
                              void* d_out, int out_size) {
    const int*   x     = (const int*)  d_in[0];
    const float* emb   = (const float*)d_in[1];
    const float* Wih_f = (const float*)d_in[2];
    const float* Whh_f = (const float*)d_in[3];
    const float* b_f   = (const float*)d_in[4];
    const float* Wih_b = (const float*)d_in[5];
    const float* Whh_b = (const float*)d_in[6];
    const float* b_b   = (const float*)d_in[7];
    const float* W_lin = (const float*)d_in[8];
    const float* b_lin = (const float*)d_in[9];
    float* out = (float*)d_out;

    cudaFuncSetAttribute(lstm_rec_kernel,
                         cudaFuncAttributeMaxDynamicSharedMemorySize, REC_SMEM);

    // K1: vocab projection. grid = (N tiles, M tiles, dir)
    {
        dim3 grid((G4 + K1_BN - 1) / K1_BN, Vv / K1_BM, 2);
        proj_kernel<<<grid, 256>>>(emb, Wih_f, Wih_b, b_f, b_b);
    }
    // K2: recurrence. 128 CTAs, clusters of 8.
    lstm_rec_kernel<<<128, REC_THREADS, REC_SMEM>>>(x, Whh_f, Whh_b);

    // K3: output. 65536 warps.
    {
        int warps_per_block = 8;
        int blocks = (Bb * Tt) / warps_per_block;
        out_kernel<<<blocks, warps_per_block * 32>>>(W_lin, b_lin, out);
    }
}

// round 9
// speedup vs baseline: 1.0036x; 1.0036x over previous
#include <cuda_runtime.h>
#include <cuda_bf16.h>
#include <cooperative_groups.h>
#include <cstdint>
#include <cstddef>

namespace cg = cooperative_groups;

// Problem dims
#define Vv 32000
#define Ee 300
#define Hh 300
#define G4 1200   // 4*H
#define Bb 128
#define Tt 512
#define Oo 9

// ---------------- scratch (device globals: allocation-free rule) ----------------
__device__ float g_proj[2ull * Vv * G4];          // 307.2 MB
__device__ float g_h[2ull * Bb * Tt * Hh];        // 157.3 MB

// ---------------- packed fp32x2 helpers ----------------
typedef unsigned long long ull_t;

__device__ __forceinline__ void ffma2(ull_t& d, ull_t a, ull_t b) {
    asm("fma.rn.f32x2 %0, %1, %2, %0;" : "+l"(d) : "l"(a), "l"(b));
}
union F4U { float4 f; ull_t u[2]; };
union U2F { ull_t u; float2 f; };

// ---------------- mbarrier helpers (R7 skeleton) ----------------
__device__ __forceinline__ void mbar_init(uint32_t addr, uint32_t count) {
    asm volatile("mbarrier.init.shared.b64 [%0], %1;" :: "r"(addr), "r"(count) : "memory");
}
__device__ __forceinline__ void mbar_arrive_rank(uint32_t local_mbar_addr, uint32_t rank) {
    asm volatile(
        "{\n\t"
        ".reg .b32 ra;\n\t"
        "mapa.shared::cluster.u32 ra, %0, %1;\n\t"
        "mbarrier.arrive.shared::cluster.b64 _, [ra];\n\t"
        "}"
        :: "r"(local_mbar_addr), "r"(rank) : "memory");
}
__device__ __forceinline__ void mbar_wait_parity_acq_cluster(uint32_t addr, uint32_t parity) {
    uint32_t done;
    asm volatile(
        "{\n\t"
        ".reg .pred p;\n\t"
        "mbarrier.try_wait.parity.acquire.cluster.shared::cta.b64 p, [%1], %2;\n\t"
        "selp.b32 %0, 1, 0, p;\n\t"
        "}"
        : "=r"(done) : "r"(addr), "r"(parity) : "memory");
    while (!done) {
        asm volatile(
            "{\n\t"
            ".reg .pred p;\n\t"
            "mbarrier.try_wait.parity.acquire.cluster.shared::cta.b64 p, [%1], %2, 0x989680;\n\t"
            "selp.b32 %0, 1, 0, p;\n\t"
            "}"
            : "=r"(done) : "r"(addr), "r"(parity) : "memory");
    }
}

// =================================================================
// K1: vocab projection GEMM  (known-good R2 version, untouched)
// =================================================================
#define K1_BM 128
#define K1_BN 64
#define K1_BK 16

__global__ void proj_kernel(const float* __restrict__ emb,
                            const float* __restrict__ Wf,
                            const float* __restrict__ Wb,
                            const float* __restrict__ bf,
                            const float* __restrict__ bb) {
    __shared__ float As[K1_BK][K1_BM + 4];
    __shared__ float Bs[K1_BK][K1_BN + 4];

    const int dir = blockIdx.z;
    const float* __restrict__ W    = dir ? Wb : Wf;
    const float* __restrict__ bias = dir ? bb : bf;
    const int n0 = blockIdx.x * K1_BN;
    const int m0 = blockIdx.y * K1_BM;
    const int tid = threadIdx.x;
    const int tx = tid & 15;
    const int ty = tid >> 4;

    float acc[8][4];
#pragma unroll
    for (int i = 0; i < 8; i++)
#pragma unroll
        for (int j = 0; j < 4; j++) acc[i][j] = 0.f;

    for (int kk = 0; kk < Ee; kk += K1_BK) {
#pragma unroll
        for (int it = 0; it < 2; it++) {
            int f = tid + it * 256;
            int row = f >> 2;
            int kq  = (f & 3) * 4;
            int k0  = kk + kq;
            const float* src = emb + (size_t)(m0 + row) * Ee;
            float4 v;
            if (k0 + 3 < Ee) {
                v = *(const float4*)(src + k0);
            } else {
                v.x = (k0 + 0 < Ee) ? src[k0 + 0] : 0.f;
                v.y = (k0 + 1 < Ee) ? src[k0 + 1] : 0.f;
                v.z = (k0 + 2 < Ee) ? src[k0 + 2] : 0.f;
                v.w = (k0 + 3 < Ee) ? src[k0 + 3] : 0.f;
            }
            As[kq + 0][row] = v.x; As[kq + 1][row] = v.y;
            As[kq + 2][row] = v.z; As[kq + 3][row] = v.w;
        }
        {
            int f = tid;
            int row = f >> 2;
            int kq  = (f & 3) * 4;
            int k0  = kk + kq;
            int n   = n0 + row;
            float4 v = make_float4(0.f, 0.f, 0.f, 0.f);
            if (n < G4) {
                const float* src = W + (size_t)n * Ee;
                if (k0 + 3 < Ee) {
                    v = *(const float4*)(src + k0);
                } else {
                    v.x = (k0 + 0 < Ee) ? src[k0 + 0] : 0.f;
                    v.y = (k0 + 1 < Ee) ? src[k0 + 1] : 0.f;
                    v.z = (k0 + 2 < Ee) ? src[k0 + 2] : 0.f;
                    v.w = (k0 + 3 < Ee) ? src[k0 + 3] : 0.f;
                }
            }
            Bs[kq + 0][row] = v.x; Bs[kq + 1][row] = v.y;
            Bs[kq + 2][row] = v.z; Bs[kq + 3][row] = v.w;
        }
        __syncthreads();

#pragma unroll
        for (int k = 0; k < K1_BK; k++) {
            float4 a0 = *(float4*)&As[k][ty * 8];
            float4 a1 = *(float4*)&As[k][ty * 8 + 4];
            float4 bv = *(float4*)&Bs[k][tx * 4];
            float av[8] = {a0.x, a0.y, a0.z, a0.w, a1.x, a1.y, a1.z, a1.w};
            float bvv[4] = {bv.x, bv.y, bv.z, bv.w};
#pragma unroll
            for (int i = 0; i < 8; i++)
#pragma unroll
                for (int j = 0; j < 4; j++) acc[i][j] += av[i] * bvv[j];
        }
        __syncthreads();
    }

    float* cbase = g_proj + (size_t)dir * Vv * G4;
#pragma unroll
    for (int i = 0; i < 8; i++) {
        int m = m0 + ty * 8 + i;
#pragma unroll
        for (int j = 0; j < 4; j++) {
            int n = n0 + tx * 4 + j;
            if (n < G4) cbase[(size_t)m * G4 + n] = acc[i][j] + bias[n];
        }
    }
}

// =================================================================
// K2: BiLSTM recurrence. Cluster of 8 CTAs = (dir, 16 batch rows).
// CTA rank r owns hidden slice [r*40, r*40+40).
// 640 threads = 20 warps (exactly 5 per SMSP — balanced FMA load).
// Thread decode: warp w (0..19), lane l:
//   kh  = l & 1          (k-half: k2 in [0,75) or [75,150))
//   rg  = (l >> 1) & 7   (row pair: rows 2rg, 2rg+1)
//   j   = w*2 + ((l>>4)&1)   (hidden col within slice, 0..39)
// Each thread: 2 rows x 4 gates over half of K; k-half partials
// combined with one shfl_xor(1).
// SMEM layouts (32B half-pad kills kh bank aliasing):
//   W_s2[kh][k2l 0..74][gi 0..159][2]   half stride 24008 words (192.0 KB)
//   hbuf[2][kh][k2l][r 0..15][2]        half stride 2408, buf 4808 words
// Sync skeleton: exact R7 (best known: 11.47 ms).
// =================================================================
#define REC_THREADS 640
#define WHALF_WORDS 24000                  // 75*320
#define WH_STRIDE   24008                  // +8-word pad (32B) between halves
#define W2_WORDS    (2 * WH_STRIDE)        // 48016 (8 pad at end of half 1 unused)
#define HHALF_WORDS 2400                   // 75*32
#define HH_STRIDE   2408                   // +8-word pad
#define HB_WORDS    (2 * HH_STRIDE)        // 4816 per buffer
#define REC_SMEM ((W2_WORDS + 2 * HB_WORDS) * 4)   // (48016+9632)*4 = 230592 B

__device__ __forceinline__ float sigmoidf_(float x) {
    return 1.0f / (1.0f + __expf(-x));
}
__device__ __forceinline__ float tanhf_(float x) {
    float xx = fminf(fmaxf(x, -15.f), 15.f);
    float e = __expf(-2.0f * xx);
    return (1.0f - e) / (1.0f + e);
}

// padded word offset within an h buffer for "flat" word W (flat = k2*32 + r*2 + p)
__device__ __forceinline__ unsigned hpad_word(unsigned flat) {
    return flat + ((flat >= (unsigned)(75 * 32)) ? 8u : 0u);
}

__global__ void __cluster_dims__(8, 1, 1) __launch_bounds__(REC_THREADS, 1)
lstm_rec_kernel(const int* __restrict__ x,
                const float* __restrict__ Whh_f,
                const float* __restrict__ Whh_b) {
    extern __shared__ float sm[];
    float* W_s2 = sm;                         // [kh][k2l][gi][2]
    float* hbuf0 = sm + W2_WORDS;
    float* hbuf1 = sm + W2_WORDS + HB_WORDS;
    __shared__ unsigned long long mbars[2];

    cg::cluster_group cluster = cg::this_cluster();

    const int bx   = blockIdx.x;
    const int cid  = bx >> 3;           // 0..15
    const int rank = bx & 7;            // 0..7
    const int dir  = cid >> 3;          // 0,1
    const int bg   = cid & 7;           // 0..7
    const int b0   = bg * 16;
    const int h0   = rank * 40;
    const int tid  = threadIdx.x;
    const int lane = tid & 31;
    const int warp = tid >> 5;

    const int kh   = lane & 1;                      // k-half
    const int rg   = (lane >> 1) & 7;               // row pair 0..7
    const int j    = warp * 2 + ((lane >> 4) & 1);  // 0..39
    const bool validh = (h0 + j) < Hh;
    const int hjc = validh ? (h0 + j) : (Hh - 1);

    const float* __restrict__ Whh = dir ? Whh_b : Whh_f;

    const uint32_t mbar_addr0 = (uint32_t)__cvta_generic_to_shared(&mbars[0]);
    const uint32_t mbar_addr1 = (uint32_t)__cvta_generic_to_shared(&mbars[1]);

    if (tid == 0) {
        mbar_init(mbar_addr0, 8);
        mbar_init(mbar_addr1, 8);
    }

    // ---- load weight slice into SMEM (threads 0..159 each own one gi row) ----
    if (tid < 160) {
        int gi = tid;                    // gi = g*40 + jj
        int g  = gi / 40;
        int jj = gi % 40;
        bool v = (h0 + jj) < Hh;
        const float* wrow = Whh + (size_t)(g * Hh + (v ? (h0 + jj) : 0)) * Hh;
        for (int k4 = 0; k4 < Hh; k4 += 4) {
            float4 w = v ? *(const float4*)(wrow + k4) : make_float4(0.f, 0.f, 0.f, 0.f);
            int k2 = k4 >> 1;          // even
            // k2 and k2+1
            int kha = (k2 >= 75) ? 1 : 0;
            int k2la = k2 - kha * 75;
            int khb = (k2 + 1 >= 75) ? 1 : 0;
            int k2lb = (k2 + 1) - khb * 75;
            *(float2*)(W_s2 + kha * WH_STRIDE + k2la * 320 + gi * 2) = make_float2(w.x, w.y);
            *(float2*)(W_s2 + khb * WH_STRIDE + k2lb * 320 + gi * 2) = make_float2(w.z, w.w);
        }
    }
    // ---- zero h buffers (incl. pads) ----
    for (int i = tid; i < 2 * HB_WORDS; i += REC_THREADS) hbuf0[i] = 0.f;
    __syncthreads();
    cluster.sync();   // barriers + zeroed buffers visible cluster-wide

    // two batch rows per thread
    const int* xrA = x + (size_t)(b0 + rg * 2 + 0) * Tt;
    const int* xrB = x + (size_t)(b0 + rg * 2 + 1) * Tt;
    const float* ptab = g_proj + (size_t)dir * Vv * G4;

    float cA = 0.f, cB = 0.f;

    // gate-loop base pointers
    const float* wk0 = W_s2 + kh * WH_STRIDE + (0 * 40 + j) * 2;
    const float* wk1 = W_s2 + kh * WH_STRIDE + (1 * 40 + j) * 2;
    const float* wk2 = W_s2 + kh * WH_STRIDE + (2 * 40 + j) * 2;
    const float* wk3 = W_s2 + kh * WH_STRIDE + (3 * 40 + j) * 2;
    const unsigned hb_off = (unsigned)kh * HH_STRIDE + (unsigned)rg * 4;

    // staging (kh==0 lanes): padded words for (h0+j, rows 2rg / 2rg+1)
    const unsigned stageA = hpad_word((((unsigned)(h0 + j) >> 1) * 32) + ((unsigned)(h0 + j) & 1) + (unsigned)(rg * 2 + 0) * 2);
    const unsigned stageB = hpad_word((((unsigned)(h0 + j) >> 1) * 32) + ((unsigned)(h0 + j) & 1) + (unsigned)(rg * 2 + 1) * 2);

    // push mapping: own slice flat words [h0*16, h0*16+slice_words), float4 per thread
    const int slice_words = (rank == 7) ? 320 : 640;
    const bool do_push = (tid * 4) < slice_words;
    const unsigned push_word = hpad_word((unsigned)(h0 * 16) + (unsigned)tid * 4);

    uint32_t par0 = 0, par1 = 0;

    // ---- prologue: xp for step 0 (2 rows x 4 gates) ----
    float xp[8];
    {
        const int t0 = dir ? (Tt - 1) : 0;
        const float* pA = ptab + (size_t)xrA[t0] * G4 + hjc;
        const float* pB = ptab + (size_t)xrB[t0] * G4 + hjc;
#pragma unroll
        for (int g = 0; g < 4; g++) { xp[g] = pA[g * Hh]; xp[4 + g] = pB[g * Hh]; }
    }

    for (int ti = 0; ti < Tt; ti++) {
        const int tcur = dir ? (Tt - 1 - ti) : ti;
        float* hcur  = (ti & 1) ? hbuf1 : hbuf0;
        float* hnext = (ti & 1) ? hbuf0 : hbuf1;

        // ---- prefetch next xp (before the wait; latency hidden) ----
        float xpn[8];
        {
            const int tin = (ti + 1 < Tt) ? (ti + 1) : ti;
            const int tn  = dir ? (Tt - 1 - tin) : tin;
            const float* pA = ptab + (size_t)xrA[tn] * G4 + hjc;
            const float* pB = ptab + (size_t)xrB[tn] * G4 + hjc;
#pragma unroll
            for (int g = 0; g < 4; g++) { xpn[g] = pA[g * Hh]; xpn[4 + g] = pB[g * Hh]; }
        }

        // ---- wait for h of step ti-1 ----
        if (ti > 0) {
            if (ti & 1) { mbar_wait_parity_acq_cluster(mbar_addr1, par1); par1 ^= 1; }
            else        { mbar_wait_parity_acq_cluster(mbar_addr0, par0); par0 ^= 1; }
        }

        // ---- gate dots: a2[row(2)][gate(4)], f32x2 over k-pairs, half-K ----
        const float* hbp = hcur + hb_off;
        ull_t a2[8];
#pragma unroll
        for (int i = 0; i < 8; i++) a2[i] = 0ull;

#pragma unroll 3
        for (int k2l = 0; k2l < 75; k2l++) {
            ull_t w0 = *(const ull_t*)(wk0 + k2l * 320);
            ull_t w1 = *(const ull_t*)(wk1 + k2l * 320);
            ull_t w2 = *(const ull_t*)(wk2 + k2l * 320);
            ull_t w3 = *(const ull_t*)(wk3 + k2l * 320);
            F4U hv; hv.f = *(const float4*)(hbp + k2l * 32);
            ffma2(a2[0], hv.u[0], w0); ffma2(a2[1], hv.u[0], w1);
            ffma2(a2[2], hv.u[0], w2); ffma2(a2[3], hv.u[0], w3);
            ffma2(a2[4], hv.u[1], w0); ffma2(a2[5], hv.u[1], w1);
            ffma2(a2[6], hv.u[1], w2); ffma2(a2[7], hv.u[1], w3);
        }

        // collapse pairs + combine k-halves (partner lane = lane^1)
        float s[8];
#pragma unroll
        for (int i = 0; i < 8; i++) {
            U2F v; v.u = a2[i];
            s[i] = v.f.x + v.f.y;
        }
#pragma unroll
        for (int i = 0; i < 8; i++)
            s[i] += __shfl_xor_sync(0xFFFFFFFFu, s[i], 1);

        // ---- LSTM cell update (both kh lanes redundantly; c in regs) ----
        float hnA, hnB;
        {
            float gi_, gf_, gg_, go_, tg;
            gi_ = s[0] + xp[0]; gf_ = s[1] + xp[1]; gg_ = s[2] + xp[2]; go_ = s[3] + xp[3];
            tg = tanhf_(gg_); cA = sigmoidf_(gf_) * cA + sigmoidf_(gi_) * tg; hnA = sigmoidf_(go_) * tanhf_(cA);
            gi_ = s[4] + xp[4]; gf_ = s[5] + xp[5]; gg_ = s[6] + xp[6]; go_ = s[7] + xp[7];
            tg = tanhf_(gg_); cB = sigmoidf_(gf_) * cB + sigmoidf_(gi_) * tg; hnB = sigmoidf_(go_) * tanhf_(cB);
        }

        // ---- write h to global for the output stage (kh==0 lanes) ----
        if (kh == 0 && validh) {
            size_t baseA = ((size_t)(dir * Bb + b0 + rg * 2 + 0) * Tt + tcur) * Hh + (h0 + j);
            size_t baseB = ((size_t)(dir * Bb + b0 + rg * 2 + 1) * Tt + tcur) * Hh + (h0 + j);
            g_h[baseA] = hnA;
            g_h[baseB] = hnB;
        }

        if (ti + 1 < Tt) {
            // ---- stage new h into NEXT buffer (kh==0 lanes) ----
            if (kh == 0 && validh) {
                hnext[stageA] = hnA;
                hnext[stageB] = hnB;
            }
            __syncthreads();

            // ---- push own slice to 7 peers (float4 per thread) ----
            if (do_push) {
                float4 v = *(const float4*)(hnext + push_word);
#pragma unroll
                for (int rr = 0; rr < 8; rr++) {
                    if (rr == rank) continue;
                    float* ph = cluster.map_shared_rank(hnext, rr);
                    *(float4*)(ph + push_word) = v;
                }
            }

            // ---- aggregated release-arrive on all 8 CTAs' barriers ----
            if (tid == 0) {
                asm volatile("fence.acq_rel.cluster;" ::: "memory");
                const uint32_t mb = (ti & 1) ? mbar_addr0 : mbar_addr1;
#pragma unroll
                for (int rr = 0; rr < 8; rr++) mbar_arrive_rank(mb, rr);
            }
        }

#pragma unroll
        for (int i = 0; i < 8; i++) xp[i] = xpn[i];
    }
}

// =================================================================
// K3: output linear + softmax. One warp per (b,t).
// =================================================================
__global__ void out_kernel(const float* __restrict__ W_lin,
                           const float* __restrict__ b_lin,
                           float* __restrict__ out) {
    const int warp = (blockIdx.x * blockDim.x + threadIdx.x) >> 5;
    const int lane = threadIdx.x & 31;
    if (warp >= Bb * Tt) return;
    const int b = warp / Tt;
    const int t = warp % Tt;

    const float* hf = g_h + ((size_t)(0 * Bb + b) * Tt + t) * Hh;
    const float* hb = g_h + ((size_t)(1 * Bb + b) * Tt + t) * Hh;

    float acc[Oo];
#pragma unroll
    for (int o = 0; o < Oo; o++) acc[o] = 0.f;

    for (int k = lane; k < Hh; k += 32) {
        float a = hf[k];
        float c = hb[k];
#pragma unroll
        for (int o = 0; o < Oo; o++)
            acc[o] += a * W_lin[o * (2 * Hh) + k] + c * W_lin[o * (2 * Hh) + Hh + k];
    }
#pragma unroll
    for (int o = 0; o < Oo; o++) {
#pragma unroll
        for (int off = 16; off > 0; off >>= 1)
            acc[o] += __shfl_xor_sync(0xFFFFFFFFu, acc[o], off);
        acc[o] += b_lin[o];
    }
    float mx = acc[0];
#pragma unroll
    for (int o = 1; o < Oo; o++) mx = fmaxf(mx, acc[o]);
    float s = 0.f;
    float e[Oo];
#pragma unroll
    for (int o = 0; o < Oo; o++) { e[o] = __expf(acc[o] - mx); s += e[o]; }
    float inv = 1.0f / s;
    if (lane < Oo) out[(size_t)warp * Oo + lane] = e[lane] * inv;
}

// =================================================================
// launcher
// =================================================================
extern "C" void kernel_launch(void* const* d_in, const int* in_sizes, int n_in,
                              void* d_out, int out_size) {
    const int*   x     = (const int*)  d_in[0];
    const float* emb   = (const float*)d_in[1];
    const float* Wih_f = (const float*)d_in[2];
    const float* Whh_f = (const float*)d_in[3];
    const float* b_f   = (const float*)d_in[4];
    const float* Wih_b = (const float*)d_in[5];
    const float* Whh_b = (const float*)d_in[6];
    const float* b_b   = (const float*)d_in[7];
    const float* W_lin = (const float*)d_in[8];
    const float* b_lin = (const float*)d_in[9];
    float* out = (float*)d_out;

    cudaFuncSetAttribute(lstm_rec_kernel,
                         cudaFuncAttributeMaxDynamicSharedMemorySize, REC_SMEM);

    // K1: vocab projection. grid = (N tiles, M tiles, dir)
    {
        dim3 grid((G4 + K1_BN - 1) / K1_BN, Vv / K1_BM, 2);
        proj_kernel<<<grid, 256>>>(emb, Wih_f, Wih_b, b_f, b_b);
    }
    // K2: recurrence. 128 CTAs, clusters of 8, 640 threads.
    lstm_rec_kernel<<<128, REC_THREADS, REC_SMEM>>>(x, Whh_f, Whh_b);

    // K3: output. 65536 warps.
    {
        int warps_per_block = 8;
        int blocks = (Bb * Tt) / warps_per_block;
        out_kernel<<<blocks, warps_per_block * 32>>>(W_lin, b_lin, out);
    }
}

// round 12
// speedup vs baseline: 1.1973x; 1.1930x over previous
#include <cuda_runtime.h>
#include <cuda_bf16.h>
#include <cooperative_groups.h>
#include <cstdint>
#include <cstddef>
#include <cstring>

namespace cg = cooperative_groups;

// Problem dims
#define Vv 32000
#define Ee 300
#define Hh 300
#define G4 1200   // 4*H
#define Bb 128
#define Tt 512
#define Oo 9
#define KP 320    // K padded (300 -> 320)
#define KC 160    // KP/2 u32 cells per row

// ---------------- scratch (device globals: allocation-free rule) ----------------
__device__ float g_proj[2ull * Vv * G4];          // 307.2 MB
__device__ float g_h[2ull * Bb * Tt * Hh];        // 157.3 MB
// bf16 hi/lo splits (u32 = 2 packed bf16 along K)
__device__ unsigned g_emb_hi[(size_t)Vv * KC];
__device__ unsigned g_emb_lo[(size_t)Vv * KC];
__device__ unsigned g_wih_hi[2ull * G4 * KC];
__device__ unsigned g_wih_lo[2ull * G4 * KC];

// ---------------- packed fp32x2 helpers ----------------
typedef unsigned long long ull_t;

__device__ __forceinline__ void ffma2(ull_t& d, ull_t a, ull_t b) {
    asm("fma.rn.f32x2 %0, %1, %2, %0;" : "+l"(d) : "l"(a), "l"(b));
}
union F4U { float4 f; ull_t u[2]; };
union U2F { ull_t u; float2 f; };

// ---------------- warp-level bf16 MMA (portable PTX, sm_80+) ----------------
__device__ __forceinline__ void mma16816(float* c, const unsigned* a, const unsigned* b) {
    asm volatile(
        "mma.sync.aligned.m16n8k16.row.col.f32.bf16.bf16.f32 "
        "{%0,%1,%2,%3}, {%4,%5,%6,%7}, {%8,%9}, {%0,%1,%2,%3};"
        : "+f"(c[0]), "+f"(c[1]), "+f"(c[2]), "+f"(c[3])
        : "r"(a[0]), "r"(a[1]), "r"(a[2]), "r"(a[3]), "r"(b[0]), "r"(b[1]));
}

// =================================================================
// K0: fp32 -> bf16 hi/lo split (K 300 -> 320 zero-pad)
// =================================================================
__global__ void split_kernel(const float* __restrict__ src,
                             unsigned* __restrict__ hi,
                             unsigned* __restrict__ lo,
                             int rows) {
    size_t idx = (size_t)blockIdx.x * blockDim.x + threadIdx.x;
    size_t total = (size_t)rows * KC;
    if (idx >= total) return;
    int row = (int)(idx / KC);
    int kc  = (int)(idx % KC);
    int k0 = kc * 2, k1 = kc * 2 + 1;
    float x0 = (k0 < Ee) ? src[(size_t)row * Ee + k0] : 0.f;
    float x1 = (k1 < Ee) ? src[(size_t)row * Ee + k1] : 0.f;
    __nv_bfloat16 h0 = __float2bfloat16(x0);
    __nv_bfloat16 h1 = __float2bfloat16(x1);
    __nv_bfloat16 l0 = __float2bfloat16(x0 - __bfloat162float(h0));
    __nv_bfloat16 l1 = __float2bfloat16(x1 - __bfloat162float(h1));
    unsigned uh, ul;
    {
        unsigned short a, b;
        memcpy(&a, &h0, 2); memcpy(&b, &h1, 2); uh = (unsigned)a | ((unsigned)b << 16);
        memcpy(&a, &l0, 2); memcpy(&b, &l1, 2); ul = (unsigned)a | ((unsigned)b << 16);
    }
    hi[idx] = uh;
    lo[idx] = ul;
}

// =================================================================
// K1: proj GEMM via mma.sync bf16, 3-term hi/lo split.
// C[v][n] = emb[v][:] . W[n][:] + bias[n]
// Block: BM=128, BN=80, 256 thr (8 warps: 4m x 2n, warp tile 32x40).
// K loop: 10 blocks of 32 (16 u32 cells), 2 k16-substeps each.
// SMEM row stride 20 u32 (rows 0..7 distinct banks for frag loads).
// =================================================================
#define PJ_BM 128
#define PJ_BN 80
#define PJ_STR 20

__global__ void __launch_bounds__(256)
proj_mma_kernel(const float* __restrict__ bf,
                const float* __restrict__ bb) {
    __shared__ unsigned As_hi[PJ_BM * PJ_STR];
    __shared__ unsigned As_lo[PJ_BM * PJ_STR];
    __shared__ unsigned Bs_hi[PJ_BN * PJ_STR];
    __shared__ unsigned Bs_lo[PJ_BN * PJ_STR];

    const int tid  = threadIdx.x;
    const int wid  = tid >> 5;
    const int lane = tid & 31;
    const int wm   = wid & 3;          // 0..3 (m)
    const int wn   = wid >> 2;         // 0..1 (n)
    const int g    = lane >> 2;        // 0..7
    const int q    = lane & 3;         // 0..3

    const int n0  = blockIdx.x * PJ_BN;
    const int m0  = blockIdx.y * PJ_BM;
    const int dir = blockIdx.z;
    const float* __restrict__ bias = dir ? bb : bf;

    const unsigned* __restrict__ whi = g_wih_hi + (size_t)dir * G4 * KC;
    const unsigned* __restrict__ wlo = g_wih_lo + (size_t)dir * G4 * KC;

    float acc[2][5][4];
#pragma unroll
    for (int mt = 0; mt < 2; mt++)
#pragma unroll
        for (int nt = 0; nt < 5; nt++)
#pragma unroll
            for (int i = 0; i < 4; i++) acc[mt][nt][i] = 0.f;

    for (int kb = 0; kb < 10; kb++) {
        // ---- stage A (128 rows x 16 cells) hi+lo ----
#pragma unroll
        for (int it = 0; it < 2; it++) {
            int idx = tid + it * 256;          // 0..511
            int row = idx >> 2;
            int q4  = (idx & 3) * 4;
            size_t so = (size_t)(m0 + row) * KC + kb * 16 + q4;
            uint4 vh = *(const uint4*)(g_emb_hi + so);
            uint4 vl = *(const uint4*)(g_emb_lo + so);
            unsigned* dh = As_hi + row * PJ_STR + q4;
            unsigned* dl = As_lo + row * PJ_STR + q4;
            dh[0] = vh.x; dh[1] = vh.y; dh[2] = vh.z; dh[3] = vh.w;
            dl[0] = vl.x; dl[1] = vl.y; dl[2] = vl.z; dl[3] = vl.w;
        }
        // ---- stage B (80 rows x 16 cells) hi+lo ----
        if (tid < 160) {
#pragma unroll
            for (int it = 0; it < 2; it++) {
                int idx = tid + it * 160;      // 0..319
                int row = idx >> 2;
                int q4  = (idx & 3) * 4;
                size_t so = (size_t)(n0 + row) * KC + kb * 16 + q4;
                uint4 vh = *(const uint4*)(whi + so);
                uint4 vl = *(const uint4*)(wlo + so);
                unsigned* dh = Bs_hi + row * PJ_STR + q4;
                unsigned* dl = Bs_lo + row * PJ_STR + q4;
                dh[0] = vh.x; dh[1] = vh.y; dh[2] = vh.z; dh[3] = vh.w;
                dl[0] = vl.x; dl[1] = vl.y; dl[2] = vl.z; dl[3] = vl.w;
            }
        }
        __syncthreads();

#pragma unroll
        for (int sub = 0; sub < 2; sub++) {
            const int c0 = q + sub * 8;        // u32 cell of k-pair

            unsigned ah[2][4], al[2][4];
#pragma unroll
            for (int mt = 0; mt < 2; mt++) {
                int r = wm * 32 + mt * 16 + g;
                const unsigned* ph = As_hi + r * PJ_STR;
                const unsigned* pl = As_lo + r * PJ_STR;
                ah[mt][0] = ph[c0];
                ah[mt][1] = ph[8 * PJ_STR + c0];
                ah[mt][2] = ph[c0 + 4];
                ah[mt][3] = ph[8 * PJ_STR + c0 + 4];
                al[mt][0] = pl[c0];
                al[mt][1] = pl[8 * PJ_STR + c0];
                al[mt][2] = pl[c0 + 4];
                al[mt][3] = pl[8 * PJ_STR + c0 + 4];
            }
            unsigned bh[5][2], bl[5][2];
#pragma unroll
            for (int nt = 0; nt < 5; nt++) {
                int n = wn * 40 + nt * 8 + g;
                const unsigned* ph = Bs_hi + n * PJ_STR;
                const unsigned* pl = Bs_lo + n * PJ_STR;
                bh[nt][0] = ph[c0];  bh[nt][1] = ph[c0 + 4];
                bl[nt][0] = pl[c0];  bl[nt][1] = pl[c0 + 4];
            }
#pragma unroll
            for (int mt = 0; mt < 2; mt++)
#pragma unroll
                for (int nt = 0; nt < 5; nt++) {
                    mma16816(acc[mt][nt], ah[mt], bh[nt]);   // hi*hi
                    mma16816(acc[mt][nt], ah[mt], bl[nt]);   // hi*lo
                    mma16816(acc[mt][nt], al[mt], bh[nt]);   // lo*hi
                }
        }
        __syncthreads();
    }

    // ---- epilogue: bias + store fp32 ----
    float* cbase = g_proj + (size_t)dir * Vv * G4;
#pragma unroll
    for (int mt = 0; mt < 2; mt++) {
        int r = m0 + wm * 32 + mt * 16 + g;
#pragma unroll
        for (int nt = 0; nt < 5; nt++) {
            int n = n0 + wn * 40 + nt * 8 + q * 2;
            float b0v = bias[n], b1v = bias[n + 1];
            float2 v0 = make_float2(acc[mt][nt][0] + b0v, acc[mt][nt][1] + b1v);
            float2 v1 = make_float2(acc[mt][nt][2] + b0v, acc[mt][nt][3] + b1v);
            *(float2*)(cbase + (size_t)r * G4 + n) = v0;
            *(float2*)(cbase + (size_t)(r + 8) * G4 + n) = v1;
        }
    }
}

// =================================================================
// K2: BiLSTM recurrence — EXACT best-known version (R7, 11471.9us).
// =================================================================
__device__ __forceinline__ void mbar_init_f(uint32_t addr, uint32_t count) {
    asm volatile("mbarrier.init.shared.b64 [%0], %1;" :: "r"(addr), "r"(count) : "memory");
}
__device__ __forceinline__ void mbar_arrive_rank(uint32_t local_mbar_addr, uint32_t rank) {
    asm volatile(
        "{\n\t"
        ".reg .b32 ra;\n\t"
        "mapa.shared::cluster.u32 ra, %0, %1;\n\t"
        "mbarrier.arrive.shared::cluster.b64 _, [ra];\n\t"
        "}"
        :: "r"(local_mbar_addr), "r"(rank) : "memory");
}
__device__ __forceinline__ void mbar_wait_parity_acq_cluster(uint32_t addr, uint32_t parity) {
    uint32_t done;
    asm volatile(
        "{\n\t"
        ".reg .pred p;\n\t"
        "mbarrier.try_wait.parity.acquire.cluster.shared::cta.b64 p, [%1], %2;\n\t"
        "selp.b32 %0, 1, 0, p;\n\t"
        "}"
        : "=r"(done) : "r"(addr), "r"(parity) : "memory");
    while (!done) {
        asm volatile(
            "{\n\t"
            ".reg .pred p;\n\t"
            "mbarrier.try_wait.parity.acquire.cluster.shared::cta.b64 p, [%1], %2, 0x989680;\n\t"
            "selp.b32 %0, 1, 0, p;\n\t"
            "}"
            : "=r"(done) : "r"(addr), "r"(parity) : "memory");
    }
}

#define REC_THREADS 160
#define W2_WORDS (150 * 320)               // 48000
#define HB_WORDS (150 * 32)                // 4800 per buffer
#define REC_SMEM ((W2_WORDS + 2 * HB_WORDS) * 4)   // 230400 B

__device__ __forceinline__ float sigmoidf_(float x) {
    return 1.0f / (1.0f + __expf(-x));
}
__device__ __forceinline__ float tanhf_(float x) {
    float xx = fminf(fmaxf(x, -15.f), 15.f);
    float e = __expf(-2.0f * xx);
    return (1.0f - e) / (1.0f + e);
}

__global__ void __cluster_dims__(8, 1, 1) __launch_bounds__(REC_THREADS, 1)
lstm_rec_kernel(const int* __restrict__ x,
                const float* __restrict__ Whh_f,
                const float* __restrict__ Whh_b) {
    extern __shared__ float sm[];
    float* W_s2 = sm;                         // [k2][gi][2]
    float* hbuf0 = sm + W2_WORDS;             // [k2][r][2]
    float* hbuf1 = sm + W2_WORDS + HB_WORDS;  // [k2][r][2]
    __shared__ unsigned long long mbars[2];

    cg::cluster_group cluster = cg::this_cluster();

    const int bx   = blockIdx.x;
    const int cid  = bx >> 3;           // 0..15
    const int rank = bx & 7;            // 0..7
    const int dir  = cid >> 3;          // 0,1
    const int bg   = cid & 7;           // 0..7
    const int b0   = bg * 16;
    const int h0   = rank * 40;
    const int tid  = threadIdx.x;
    const int j    = tid % 40;
    const int rg   = tid / 40;          // 0..3
    const bool validh = (h0 + j) < Hh;
    const int hjc = validh ? (h0 + j) : (Hh - 1);

    const float* __restrict__ Whh = dir ? Whh_b : Whh_f;

    const uint32_t mbar_addr0 = (uint32_t)__cvta_generic_to_shared(&mbars[0]);
    const uint32_t mbar_addr1 = (uint32_t)__cvta_generic_to_shared(&mbars[1]);

    if (tid == 0) {
        mbar_init_f(mbar_addr0, 8);
        mbar_init_f(mbar_addr1, 8);
    }

    // ---- load weight slice into SMEM, k-pair interleaved ----
    {
        int gi = tid;                    // 0..159
        int g  = gi / 40;
        int jj = gi % 40;
        bool v = (h0 + jj) < Hh;
        const float* wrow = Whh + (size_t)(g * Hh + (v ? (h0 + jj) : 0)) * Hh;
        for (int k4 = 0; k4 < Hh; k4 += 4) {
            float4 w = v ? *(const float4*)(wrow + k4) : make_float4(0.f, 0.f, 0.f, 0.f);
            int k2 = k4 >> 1;
            *(float2*)(W_s2 + (k2 + 0) * 320 + gi * 2) = make_float2(w.x, w.y);
            *(float2*)(W_s2 + (k2 + 1) * 320 + gi * 2) = make_float2(w.z, w.w);
        }
    }
    // ---- zero h buffers ----
    for (int i = tid; i < 2 * HB_WORDS; i += REC_THREADS) hbuf0[i] = 0.f;
    __syncthreads();
    cluster.sync();

    const int* xr0 = x + (size_t)(b0 + rg * 4 + 0) * Tt;
    const int* xr1 = x + (size_t)(b0 + rg * 4 + 1) * Tt;
    const int* xr2 = x + (size_t)(b0 + rg * 4 + 2) * Tt;
    const int* xr3 = x + (size_t)(b0 + rg * 4 + 3) * Tt;
    const float* ptab = g_proj + (size_t)dir * Vv * G4;

    float c0 = 0.f, c1 = 0.f, c2 = 0.f, c3 = 0.f;

    const float* wb0 = W_s2 + (0 * 40 + j) * 2;
    const float* wb1 = W_s2 + (1 * 40 + j) * 2;
    const float* wb2 = W_s2 + (2 * 40 + j) * 2;
    const float* wb3 = W_s2 + (3 * 40 + j) * 2;
    const unsigned hb_off = (unsigned)(rg * 4) * 2;

    const unsigned stage_base = ((unsigned)(h0 + j) >> 1) * 32 + ((unsigned)(h0 + j) & 1);
    const int slice_words = (rank == 7) ? 320 : 640;
    const unsigned push_word = (unsigned)(h0 * 16) + (unsigned)tid * 4;
    const bool do_push = (tid * 4) < slice_words;

    uint32_t par0 = 0, par1 = 0;

    float xp[16];
    {
        const int t0 = dir ? (Tt - 1) : 0;
        const float* p0 = ptab + (size_t)xr0[t0] * G4 + hjc;
        const float* p1 = ptab + (size_t)xr1[t0] * G4 + hjc;
        const float* p2 = ptab + (size_t)xr2[t0] * G4 + hjc;
        const float* p3 = ptab + (size_t)xr3[t0] * G4 + hjc;
#pragma unroll
        for (int g = 0; g < 4; g++) {
            xp[0 * 4 + g] = p0[g * Hh];
            xp[1 * 4 + g] = p1[g * Hh];
            xp[2 * 4 + g] = p2[g * Hh];
            xp[3 * 4 + g] = p3[g * Hh];
        }
    }

    for (int ti = 0; ti < Tt; ti++) {
        const int tcur = dir ? (Tt - 1 - ti) : ti;
        float* hcur  = (ti & 1) ? hbuf1 : hbuf0;
        float* hnext = (ti & 1) ? hbuf0 : hbuf1;

        float xpn[16];
        {
            const int tin = (ti + 1 < Tt) ? (ti + 1) : ti;
            const int tn  = dir ? (Tt - 1 - tin) : tin;
            const float* p0 = ptab + (size_t)xr0[tn] * G4 + hjc;
            const float* p1 = ptab + (size_t)xr1[tn] * G4 + hjc;
            const float* p2 = ptab + (size_t)xr2[tn] * G4 + hjc;
            const float* p3 = ptab + (size_t)xr3[tn] * G4 + hjc;
#pragma unroll
            for (int g = 0; g < 4; g++) {
                xpn[0 * 4 + g] = p0[g * Hh];
                xpn[1 * 4 + g] = p1[g * Hh];
                xpn[2 * 4 + g] = p2[g * Hh];
                xpn[3 * 4 + g] = p3[g * Hh];
            }
        }

        if (ti > 0) {
            if (ti & 1) { mbar_wait_parity_acq_cluster(mbar_addr1, par1); par1 ^= 1; }
            else        { mbar_wait_parity_acq_cluster(mbar_addr0, par0); par0 ^= 1; }
        }

        const float* hb = hcur + hb_off;
        ull_t acc2[4][4];
#pragma unroll
        for (int r = 0; r < 4; r++)
#pragma unroll
            for (int g = 0; g < 4; g++) acc2[r][g] = 0ull;

#pragma unroll 5
        for (int k2 = 0; k2 < 150; k2++) {
            ull_t wv0 = *(const ull_t*)(wb0 + k2 * 320);
            ull_t wv1 = *(const ull_t*)(wb1 + k2 * 320);
            ull_t wv2 = *(const ull_t*)(wb2 + k2 * 320);
            ull_t wv3 = *(const ull_t*)(wb3 + k2 * 320);
            F4U h01, h23;
            h01.f = *(const float4*)(hb + k2 * 32);
            h23.f = *(const float4*)(hb + k2 * 32 + 4);
            ffma2(acc2[0][0], h01.u[0], wv0); ffma2(acc2[0][1], h01.u[0], wv1);
            ffma2(acc2[0][2], h01.u[0], wv2); ffma2(acc2[0][3], h01.u[0], wv3);
            ffma2(acc2[1][0], h01.u[1], wv0); ffma2(acc2[1][1], h01.u[1], wv1);
            ffma2(acc2[1][2], h01.u[1], wv2); ffma2(acc2[1][3], h01.u[1], wv3);
            ffma2(acc2[2][0], h23.u[0], wv0); ffma2(acc2[2][1], h23.u[0], wv1);
            ffma2(acc2[2][2], h23.u[0], wv2); ffma2(acc2[2][3], h23.u[0], wv3);
            ffma2(acc2[3][0], h23.u[1], wv0); ffma2(acc2[3][1], h23.u[1], wv1);
            ffma2(acc2[3][2], h23.u[1], wv2); ffma2(acc2[3][3], h23.u[1], wv3);
        }

        float acc[16];
#pragma unroll
        for (int r = 0; r < 4; r++)
#pragma unroll
            for (int g = 0; g < 4; g++) {
                U2F v; v.u = acc2[r][g];
                acc[r * 4 + g] = v.f.x + v.f.y;
            }

        float hn[4];
        {
            float gi_, gf_, gg_, go_, tg;
            gi_ = acc[0] + xp[0];  gf_ = acc[1] + xp[1];  gg_ = acc[2] + xp[2];  go_ = acc[3] + xp[3];
            tg = tanhf_(gg_); c0 = sigmoidf_(gf_) * c0 + sigmoidf_(gi_) * tg; hn[0] = sigmoidf_(go_) * tanhf_(c0);
            gi_ = acc[4] + xp[4];  gf_ = acc[5] + xp[5];  gg_ = acc[6] + xp[6];  go_ = acc[7] + xp[7];
            tg = tanhf_(gg_); c1 = sigmoidf_(gf_) * c1 + sigmoidf_(gi_) * tg; hn[1] = sigmoidf_(go_) * tanhf_(c1);
            gi_ = acc[8] + xp[8];  gf_ = acc[9] + xp[9];  gg_ = acc[10] + xp[10]; go_ = acc[11] + xp[11];
            tg = tanhf_(gg_); c2 = sigmoidf_(gf_) * c2 + sigmoidf_(gi_) * tg; hn[2] = sigmoidf_(go_) * tanhf_(c2);
            gi_ = acc[12] + xp[12]; gf_ = acc[13] + xp[13]; gg_ = acc[14] + xp[14]; go_ = acc[15] + xp[15];
            tg = tanhf_(gg_); c3 = sigmoidf_(gf_) * c3 + sigmoidf_(gi_) * tg; hn[3] = sigmoidf_(go_) * tanhf_(c3);
        }

        if (ti + 1 < Tt) {
            if (validh) {
                hnext[stage_base + (rg * 4 + 0) * 2] = hn[0];
                hnext[stage_base + (rg * 4 + 1) * 2] = hn[1];
                hnext[stage_base + (rg * 4 + 2) * 2] = hn[2];
                hnext[stage_base + (rg * 4 + 3) * 2] = hn[3];
            }
            __syncthreads();

            if (do_push) {
                float4 v = *(const float4*)(hnext + push_word);
#pragma unroll
                for (int rr = 0; rr < 8; rr++) {
                    if (rr == rank) continue;
                    float* ph = cluster.map_shared_rank(hnext, rr);
                    *(float4*)(ph + push_word) = v;
                }
            }

            if (tid == 0) {
                asm volatile("fence.acq_rel.cluster;" ::: "memory");
                const uint32_t mb = (ti & 1) ? mbar_addr0 : mbar_addr1;
#pragma unroll
                for (int rr = 0; rr < 8; rr++) mbar_arrive_rank(mb, rr);
            }
        }

        if (validh) {
            size_t base = ((size_t)(dir * Bb + b0 + rg * 4) * Tt + tcur) * Hh + (h0 + j);
            const size_t strideB = (size_t)Tt * Hh;
            g_h[base + 0 * strideB] = hn[0];
            g_h[base + 1 * strideB] = hn[1];
            g_h[base + 2 * strideB] = hn[2];
            g_h[base + 3 * strideB] = hn[3];
        }

        xp[0]=xpn[0]; xp[1]=xpn[1]; xp[2]=xpn[2]; xp[3]=xpn[3];
        xp[4]=xpn[4]; xp[5]=xpn[5]; xp[6]=xpn[6]; xp[7]=xpn[7];
        xp[8]=xpn[8]; xp[9]=xpn[9]; xp[10]=xpn[10]; xp[11]=xpn[11];
        xp[12]=xpn[12]; xp[13]=xpn[13]; xp[14]=xpn[14]; xp[15]=xpn[15];
    }
}

// =================================================================
// K3: output linear + softmax. One warp per (b,t). (unchanged)
// =================================================================
__global__ void out_kernel(const float* __restrict__ W_lin,
                           const float* __restrict__ b_lin,
                           float* __restrict__ out) {
    const int warp = (blockIdx.x * blockDim.x + threadIdx.x) >> 5;
    const int lane = threadIdx.x & 31;
    if (warp >= Bb * Tt) return;
    const int b = warp / Tt;
    const int t = warp % Tt;

    const float* hf = g_h + ((size_t)(0 * Bb + b) * Tt + t) * Hh;
    const float* hb = g_h + ((size_t)(1 * Bb + b) * Tt + t) * Hh;

    float acc[Oo];
#pragma unroll
    for (int o = 0; o < Oo; o++) acc[o] = 0.f;

    for (int k = lane; k < Hh; k += 32) {
        float a = hf[k];
        float c = hb[k];
#pragma unroll
        for (int o = 0; o < Oo; o++)
            acc[o] += a * W_lin[o * (2 * Hh) + k] + c * W_lin[o * (2 * Hh) + Hh + k];
    }
#pragma unroll
    for (int o = 0; o < Oo; o++) {
#pragma unroll
        for (int off = 16; off > 0; off >>= 1)
            acc[o] += __shfl_xor_sync(0xFFFFFFFFu, acc[o], off);
        acc[o] += b_lin[o];
    }
    float mx = acc[0];
#pragma unroll
    for (int o = 1; o < Oo; o++) mx = fmaxf(mx, acc[o]);
    float s = 0.f;
    float e[Oo];
#pragma unroll
    for (int o = 0; o < Oo; o++) { e[o] = __expf(acc[o] - mx); s += e[o]; }
    float inv = 1.0f / s;
    if (lane < Oo) out[(size_t)warp * Oo + lane] = e[lane] * inv;
}

// =================================================================
// launcher
// =================================================================
extern "C" void kernel_launch(void* const* d_in, const int* in_sizes, int n_in,
                              void* d_out, int out_size) {
    const int*   x     = (const int*)  d_in[0];
    const float* emb   = (const float*)d_in[1];
    const float* Wih_f = (const float*)d_in[2];
    const float* Whh_f = (const float*)d_in[3];
    const float* b_f   = (const float*)d_in[4];
    const float* Wih_b = (const float*)d_in[5];
    const float* Whh_b = (const float*)d_in[6];
    const float* b_b   = (const float*)d_in[7];
    const float* W_lin = (const float*)d_in[8];
    const float* b_lin = (const float*)d_in[9];
    float* out = (float*)d_out;

    cudaFuncSetAttribute(lstm_rec_kernel,
                         cudaFuncAttributeMaxDynamicSharedMemorySize, REC_SMEM);

    // resolve device-global scratch addresses (host API, not an allocation)
    static unsigned *p_emb_hi = nullptr, *p_emb_lo = nullptr, *p_wih_hi = nullptr, *p_wih_lo = nullptr;
    if (!p_emb_hi) {
        cudaGetSymbolAddress((void**)&p_emb_hi, g_emb_hi);
        cudaGetSymbolAddress((void**)&p_emb_lo, g_emb_lo);
        cudaGetSymbolAddress((void**)&p_wih_hi, g_wih_hi);
        cudaGetSymbolAddress((void**)&p_wih_lo, g_wih_lo);
    }

    // K0: hi/lo splits
    {
        size_t cells = (size_t)Vv * KC;
        split_kernel<<<(unsigned)((cells + 255) / 256), 256>>>(emb, p_emb_hi, p_emb_lo, Vv);
        size_t wc = (size_t)G4 * KC;
        split_kernel<<<(unsigned)((wc + 255) / 256), 256>>>(Wih_f, p_wih_hi, p_wih_lo, G4);
        split_kernel<<<(unsigned)((wc + 255) / 256), 256>>>(Wih_b, p_wih_hi + wc, p_wih_lo + wc, G4);
    }

    // K1: proj via mma.sync bf16. grid = (15 n-tiles, 250 m-tiles, 2 dirs)
    {
        dim3 grid(G4 / PJ_BN, Vv / PJ_BM, 2);
        proj_mma_kernel<<<grid, 256>>>(b_f, b_b);
    }

    // K2: recurrence. 128 CTAs, clusters of 8. (frozen best-known)
    lstm_rec_kernel<<<128, REC_THREADS, REC_SMEM>>>(x, Whh_f, Whh_b);

    // K3: output. 65536 warps.
    {
        int warps_per_block = 8;
        int blocks = (Bb * Tt) / warps_per_block;
        out_kernel<<<blocks, warps_per_block * 32>>>(W_lin, b_lin, out);
    }
}

// round 15
// speedup vs baseline: 1.9704x; 1.6457x over previous
#include <cuda_runtime.h>
#include <cuda_bf16.h>
#include <cooperative_groups.h>
#include <cstdint>
#include <cstddef>
#include <cstring>

namespace cg = cooperative_groups;

// Problem dims
#define Vv 32000
#define Ee 300
#define Hh 300
#define G4 1200   // 4*H
#define Bb 128
#define Tt 512
#define Oo 9
#define KP 320    // K padded (300 -> 320) for proj
#define KC 160    // KP/2 u32 cells per row (proj)

// ---------------- scratch (device globals: allocation-free rule) ----------------
__device__ float g_proj[2ull * Vv * G4];          // 307.2 MB
__device__ float g_h[2ull * Bb * Tt * Hh];        // 157.3 MB
// bf16 hi/lo splits (u32 = 2 packed bf16 along K)
__device__ unsigned g_emb_hi[(size_t)Vv * KC];
__device__ unsigned g_emb_lo[(size_t)Vv * KC];
__device__ unsigned g_wih_hi[2ull * G4 * KC];
__device__ unsigned g_wih_lo[2ull * G4 * KC];

typedef unsigned long long ull_t;

// ---------------- warp-level bf16 MMA (portable PTX, sm_80+) ----------------
__device__ __forceinline__ void mma16816(float* c, const unsigned* a, const unsigned* b) {
    asm volatile(
        "mma.sync.aligned.m16n8k16.row.col.f32.bf16.bf16.f32 "
        "{%0,%1,%2,%3}, {%4,%5,%6,%7}, {%8,%9}, {%0,%1,%2,%3};"
        : "+f"(c[0]), "+f"(c[1]), "+f"(c[2]), "+f"(c[3])
        : "r"(a[0]), "r"(a[1]), "r"(a[2]), "r"(a[3]), "r"(b[0]), "r"(b[1]));
}

__device__ __forceinline__ unsigned pack_bf16x2(float lo_val, float hi_val) {
    __nv_bfloat16 l = __float2bfloat16(lo_val);
    __nv_bfloat16 h = __float2bfloat16(hi_val);
    unsigned short a, b;
    memcpy(&a, &l, 2); memcpy(&b, &h, 2);
    return (unsigned)a | ((unsigned)b << 16);
}

// =================================================================
// K0: fp32 -> bf16 hi/lo split (K 300 -> 320 zero-pad)  [proj inputs]
// =================================================================
__global__ void split_kernel(const float* __restrict__ src,
                             unsigned* __restrict__ hi,
                             unsigned* __restrict__ lo,
                             int rows) {
    size_t idx = (size_t)blockIdx.x * blockDim.x + threadIdx.x;
    size_t total = (size_t)rows * KC;
    if (idx >= total) return;
    int row = (int)(idx / KC);
    int kc  = (int)(idx % KC);
    int k0 = kc * 2, k1 = kc * 2 + 1;
    float x0 = (k0 < Ee) ? src[(size_t)row * Ee + k0] : 0.f;
    float x1 = (k1 < Ee) ? src[(size_t)row * Ee + k1] : 0.f;
    __nv_bfloat16 h0 = __float2bfloat16(x0);
    __nv_bfloat16 h1 = __float2bfloat16(x1);
    __nv_bfloat16 l0 = __float2bfloat16(x0 - __bfloat162float(h0));
    __nv_bfloat16 l1 = __float2bfloat16(x1 - __bfloat162float(h1));
    unsigned uh, ul;
    {
        unsigned short a, b;
        memcpy(&a, &h0, 2); memcpy(&b, &h1, 2); uh = (unsigned)a | ((unsigned)b << 16);
        memcpy(&a, &l0, 2); memcpy(&b, &l1, 2); ul = (unsigned)a | ((unsigned)b << 16);
    }
    hi[idx] = uh;
    lo[idx] = ul;
}

// =================================================================
// K1: proj GEMM via mma.sync bf16, 3-term hi/lo split. (R12, unchanged)
// =================================================================
#define PJ_BM 128
#define PJ_BN 80
#define PJ_STR 20

__global__ void __launch_bounds__(256)
proj_mma_kernel(const float* __restrict__ bf,
                const float* __restrict__ bb) {
    __shared__ unsigned As_hi[PJ_BM * PJ_STR];
    __shared__ unsigned As_lo[PJ_BM * PJ_STR];
    __shared__ unsigned Bs_hi[PJ_BN * PJ_STR];
    __shared__ unsigned Bs_lo[PJ_BN * PJ_STR];

    const int tid  = threadIdx.x;
    const int wid  = tid >> 5;
    const int lane = tid & 31;
    const int wm   = wid & 3;
    const int wn   = wid >> 2;
    const int g    = lane >> 2;
    const int q    = lane & 3;

    const int n0  = blockIdx.x * PJ_BN;
    const int m0  = blockIdx.y * PJ_BM;
    const int dir = blockIdx.z;
    const float* __restrict__ bias = dir ? bb : bf;

    const unsigned* __restrict__ whi = g_wih_hi + (size_t)dir * G4 * KC;
    const unsigned* __restrict__ wlo = g_wih_lo + (size_t)dir * G4 * KC;

    float acc[2][5][4];
#pragma unroll
    for (int mt = 0; mt < 2; mt++)
#pragma unroll
        for (int nt = 0; nt < 5; nt++)
#pragma unroll
            for (int i = 0; i < 4; i++) acc[mt][nt][i] = 0.f;

    for (int kb = 0; kb < 10; kb++) {
#pragma unroll
        for (int it = 0; it < 2; it++) {
            int idx = tid + it * 256;
            int row = idx >> 2;
            int q4  = (idx & 3) * 4;
            size_t so = (size_t)(m0 + row) * KC + kb * 16 + q4;
            uint4 vh = *(const uint4*)(g_emb_hi + so);
            uint4 vl = *(const uint4*)(g_emb_lo + so);
            unsigned* dh = As_hi + row * PJ_STR + q4;
            unsigned* dl = As_lo + row * PJ_STR + q4;
            dh[0] = vh.x; dh[1] = vh.y; dh[2] = vh.z; dh[3] = vh.w;
            dl[0] = vl.x; dl[1] = vl.y; dl[2] = vl.z; dl[3] = vl.w;
        }
        if (tid < 160) {
#pragma unroll
            for (int it = 0; it < 2; it++) {
                int idx = tid + it * 160;
                int row = idx >> 2;
                int q4  = (idx & 3) * 4;
                size_t so = (size_t)(n0 + row) * KC + kb * 16 + q4;
                uint4 vh = *(const uint4*)(whi + so);
                uint4 vl = *(const uint4*)(wlo + so);
                unsigned* dh = Bs_hi + row * PJ_STR + q4;
                unsigned* dl = Bs_lo + row * PJ_STR + q4;
                dh[0] = vh.x; dh[1] = vh.y; dh[2] = vh.z; dh[3] = vh.w;
                dl[0] = vl.x; dl[1] = vl.y; dl[2] = vl.z; dl[3] = vl.w;
            }
        }
        __syncthreads();

#pragma unroll
        for (int sub = 0; sub < 2; sub++) {
            const int c0 = q + sub * 8;
            unsigned ah[2][4], al[2][4];
#pragma unroll
            for (int mt = 0; mt < 2; mt++) {
                int r = wm * 32 + mt * 16 + g;
                const unsigned* ph = As_hi + r * PJ_STR;
                const unsigned* pl = As_lo + r * PJ_STR;
                ah[mt][0] = ph[c0];
                ah[mt][1] = ph[8 * PJ_STR + c0];
                ah[mt][2] = ph[c0 + 4];
                ah[mt][3] = ph[8 * PJ_STR + c0 + 4];
                al[mt][0] = pl[c0];
                al[mt][1] = pl[8 * PJ_STR + c0];
                al[mt][2] = pl[c0 + 4];
                al[mt][3] = pl[8 * PJ_STR + c0 + 4];
            }
            unsigned bh[5][2], bl[5][2];
#pragma unroll
            for (int nt = 0; nt < 5; nt++) {
                int n = wn * 40 + nt * 8 + g;
                const unsigned* ph = Bs_hi + n * PJ_STR;
                const unsigned* pl = Bs_lo + n * PJ_STR;
                bh[nt][0] = ph[c0];  bh[nt][1] = ph[c0 + 4];
                bl[nt][0] = pl[c0];  bl[nt][1] = pl[c0 + 4];
            }
#pragma unroll
            for (int mt = 0; mt < 2; mt++)
#pragma unroll
                for (int nt = 0; nt < 5; nt++) {
                    mma16816(acc[mt][nt], ah[mt], bh[nt]);
                    mma16816(acc[mt][nt], ah[mt], bl[nt]);
                    mma16816(acc[mt][nt], al[mt], bh[nt]);
                }
        }
        __syncthreads();
    }

    float* cbase = g_proj + (size_t)dir * Vv * G4;
#pragma unroll
    for (int mt = 0; mt < 2; mt++) {
        int r = m0 + wm * 32 + mt * 16 + g;
#pragma unroll
        for (int nt = 0; nt < 5; nt++) {
            int n = n0 + wn * 40 + nt * 8 + q * 2;
            float b0v = bias[n], b1v = bias[n + 1];
            float2 v0 = make_float2(acc[mt][nt][0] + b0v, acc[mt][nt][1] + b1v);
            float2 v1 = make_float2(acc[mt][nt][2] + b0v, acc[mt][nt][3] + b1v);
            *(float2*)(cbase + (size_t)r * G4 + n) = v0;
            *(float2*)(cbase + (size_t)(r + 8) * G4 + n) = v1;
        }
    }
}

// =================================================================
// K2: BiLSTM recurrence with mma.sync bf16 gate GEMM.
// Cluster of 8 CTAs = (dir, 16 batch rows); CTA rank r owns hidden
// slice [r*40, r*40+40). 160 threads, 5 MMA warps; warp w owns
// j-group [8w, 8w+8) across all 4 gates (activations in-fragment).
// SMEM (u32 words):
//   Whi [160 rows x stride 150] + 2 pad  = 24002   (alias k-pad trick)
//   Wlo same                              = 24002
//   hbuf[2]: hi [16 x 152] + lo [16 x 152] = 2 x 4864
// Per-element products at k>=300 vanish because h pad cells are zero.
// Sync skeleton: exact R7 (proven).
// =================================================================
#define REC_THREADS 160
#define W_STR   150
#define WHALF   24002
#define H_STR   152
#define HHALF   2432
#define HBUFW   4864
#define HBASE   (2 * WHALF)                 // 48004
#define REC_WORDS (2 * WHALF + 2 * HBUFW)   // 57732
#define REC_SMEM (REC_WORDS * 4)            // 230928 B

__device__ __forceinline__ void mbar_init_f(uint32_t addr, uint32_t count) {
    asm volatile("mbarrier.init.shared.b64 [%0], %1;" :: "r"(addr), "r"(count) : "memory");
}
__device__ __forceinline__ void mbar_arrive_rank(uint32_t local_mbar_addr, uint32_t rank) {
    asm volatile(
        "{\n\t"
        ".reg .b32 ra;\n\t"
        "mapa.shared::cluster.u32 ra, %0, %1;\n\t"
        "mbarrier.arrive.shared::cluster.b64 _, [ra];\n\t"
        "}"
        :: "r"(local_mbar_addr), "r"(rank) : "memory");
}
__device__ __forceinline__ void mbar_wait_parity_acq_cluster(uint32_t addr, uint32_t parity) {
    uint32_t done;
    asm volatile(
        "{\n\t"
        ".reg .pred p;\n\t"
        "mbarrier.try_wait.parity.acquire.cluster.shared::cta.b64 p, [%1], %2;\n\t"
        "selp.b32 %0, 1, 0, p;\n\t"
        "}"
        : "=r"(done) : "r"(addr), "r"(parity) : "memory");
    while (!done) {
        asm volatile(
            "{\n\t"
            ".reg .pred p;\n\t"
            "mbarrier.try_wait.parity.acquire.cluster.shared::cta.b64 p, [%1], %2, 0x989680;\n\t"
            "selp.b32 %0, 1, 0, p;\n\t"
            "}"
            : "=r"(done) : "r"(addr), "r"(parity) : "memory");
    }
}

__device__ __forceinline__ float sigmoidf_(float x) {
    return 1.0f / (1.0f + __expf(-x));
}
__device__ __forceinline__ float tanhf_(float x) {
    float xx = fminf(fmaxf(x, -15.f), 15.f);
    float e = __expf(-2.0f * xx);
    return (1.0f - e) / (1.0f + e);
}

__global__ void __cluster_dims__(8, 1, 1) __launch_bounds__(REC_THREADS, 1)
lstm_rec_kernel(const int* __restrict__ x,
                const float* __restrict__ Whh_f,
                const float* __restrict__ Whh_b) {
    extern __shared__ unsigned smu[];
    __shared__ unsigned long long mbars[2];

    cg::cluster_group cluster = cg::this_cluster();

    const int bx   = blockIdx.x;
    const int cid  = bx >> 3;           // 0..15
    const int rank = bx & 7;            // 0..7
    const int dir  = cid >> 3;          // 0,1
    const int bg   = cid & 7;           // 0..7
    const int b0   = bg * 16;
    const int h0   = rank * 40;
    const int h0c  = rank * 20;         // cell offset of own slice
    const int tid  = threadIdx.x;
    const int warp = tid >> 5;          // 0..4
    const int lane = tid & 31;
    const int gg_  = lane >> 2;         // 0..7 (fragment row group)
    const int q    = lane & 3;          // 0..3

    const float* __restrict__ Whh = dir ? Whh_b : Whh_f;

    const uint32_t mbar_addr0 = (uint32_t)__cvta_generic_to_shared(&mbars[0]);
    const uint32_t mbar_addr1 = (uint32_t)__cvta_generic_to_shared(&mbars[1]);

    if (tid == 0) {
        mbar_init_f(mbar_addr0, 8);
        mbar_init_f(mbar_addr1, 8);
    }

    // ---- zero all SMEM (h buffers + W pads must be zero) ----
    for (int i = tid; i < REC_WORDS; i += REC_THREADS) smu[i] = 0u;
    __syncthreads();

    // ---- load + split W slice: row gi = gate*40 + jj, stride 150 cells ----
    {
        int gi = tid;                    // 0..159
        int gt = gi / 40;
        int jj = gi % 40;
        bool v = (h0 + jj) < Hh;
        const float* wrow = Whh + (size_t)(gt * Hh + (v ? (h0 + jj) : 0)) * Hh;
        unsigned* whi = smu + gi * W_STR;
        unsigned* wlo = smu + WHALF + gi * W_STR;
        for (int k4 = 0; k4 < Hh; k4 += 4) {
            float4 w = v ? *(const float4*)(wrow + k4) : make_float4(0.f, 0.f, 0.f, 0.f);
            int c = k4 >> 1;
            __nv_bfloat16 hx = __float2bfloat16(w.x), hy = __float2bfloat16(w.y);
            __nv_bfloat16 hz = __float2bfloat16(w.z), hw = __float2bfloat16(w.w);
            float lx = w.x - __bfloat162float(hx), ly = w.y - __bfloat162float(hy);
            float lz = w.z - __bfloat162float(hz), lw = w.w - __bfloat162float(hw);
            unsigned short s0, s1;
            memcpy(&s0, &hx, 2); memcpy(&s1, &hy, 2);
            whi[c]     = (unsigned)s0 | ((unsigned)s1 << 16);
            memcpy(&s0, &hz, 2); memcpy(&s1, &hw, 2);
            whi[c + 1] = (unsigned)s0 | ((unsigned)s1 << 16);
            wlo[c]     = pack_bf16x2(lx, ly);
            wlo[c + 1] = pack_bf16x2(lz, lw);
        }
    }
    __syncthreads();
    cluster.sync();   // barriers + zeroed buffers visible cluster-wide

    // batch rows for this thread's fragments
    const int rA = gg_;                  // fragment rows g, g+8
    const int rB = gg_ + 8;
    const int* xrA = x + (size_t)(b0 + rA) * Tt;
    const int* xrB = x + (size_t)(b0 + rB) * Tt;
    const float* ptab = g_proj + (size_t)dir * Vv * G4;

    // hidden cols for this thread (pair): jg, jg+1
    const int jl  = 8 * warp + 2 * q;    // 0..38 local
    const int jg  = h0 + jl;             // global even
    const int jgc = (jg <= 298) ? jg : 298;   // clamped for loads
    const bool jvalid = (jg + 1) < Hh + 1 && jg < Hh;   // jg<=298 -> both valid

    // W fragment base indices (invariant): row gi = gate*40 + 8w + g
    int wbase[4];
#pragma unroll
    for (int G = 0; G < 4; G++) wbase[G] = (G * 40 + 8 * warp + gg_) * W_STR + q;

    // A fragment offsets within an h half
    const int aoffA = rA * H_STR + q;
    const int aoffB = rB * H_STR + q;

    // staging cell for own hn pair
    const int cellA = h0c + 4 * warp + q;     // valid iff < 150
    const bool stage_ok = cellA < 150;

    // push mapping: 160 float4s cover own slice (hi+lo)
    const int p_half = tid / 80;              // 0 hi, 1 lo
    const int p_idx  = tid % 80;
    const int p_row  = p_idx / 5;
    const int p_ch   = p_idx % 5;
    const bool do_push = (rank < 7) || (p_ch < 3);
    const unsigned push_word = (unsigned)(p_half * HHALF + p_row * H_STR + h0c + p_ch * 4);

    float cA0 = 0.f, cA1 = 0.f, cB0 = 0.f, cB1 = 0.f;
    uint32_t par0 = 0, par1 = 0;

    // ---- prologue: xp for step 0: [2 rows][4 gates] float2 (js jg, jg+1) ----
    float2 xpA[4], xpB[4];
    {
        const int t0 = dir ? (Tt - 1) : 0;
        const float* pA = ptab + (size_t)xrA[t0] * G4;
        const float* pB = ptab + (size_t)xrB[t0] * G4;
#pragma unroll
        for (int G = 0; G < 4; G++) {
            xpA[G] = *(const float2*)(pA + G * Hh + jgc);
            xpB[G] = *(const float2*)(pB + G * Hh + jgc);
        }
    }

    for (int ti = 0; ti < Tt; ti++) {
        const int tcur = dir ? (Tt - 1 - ti) : ti;
        const int buf  = ti & 1;
        const unsigned hcur_base  = HBASE + buf * HBUFW;
        const unsigned hnext_base = HBASE + (buf ^ 1) * HBUFW;

        // ---- prefetch next xp (issued before the wait) ----
        float2 xpnA[4], xpnB[4];
        {
            const int tin = (ti + 1 < Tt) ? (ti + 1) : ti;
            const int tn  = dir ? (Tt - 1 - tin) : tin;
            const float* pA = ptab + (size_t)xrA[tn] * G4;
            const float* pB = ptab + (size_t)xrB[tn] * G4;
#pragma unroll
            for (int G = 0; G < 4; G++) {
                xpnA[G] = *(const float2*)(pA + G * Hh + jgc);
                xpnB[G] = *(const float2*)(pB + G * Hh + jgc);
            }
        }

        // ---- wait for h of step ti-1 ----
        if (ti > 0) {
            if (buf) { mbar_wait_parity_acq_cluster(mbar_addr1, par1); par1 ^= 1; }
            else     { mbar_wait_parity_acq_cluster(mbar_addr0, par0); par0 ^= 1; }
        }

        // ---- gate GEMM: acc[gate][4] via mma.sync, 3-term hi/lo ----
        const unsigned* hh = smu + hcur_base;            // hi half
        const unsigned* hl = smu + hcur_base + HHALF;    // lo half
        const unsigned* Wh = smu;
        const unsigned* Wl = smu + WHALF;

        float acc[4][4];
#pragma unroll
        for (int G = 0; G < 4; G++)
#pragma unroll
            for (int i = 0; i < 4; i++) acc[G][i] = 0.f;

#pragma unroll 1
        for (int kb = 0; kb < 19; kb++) {
            const int ko = kb * 8;
            unsigned a_hi[4], a_lo[4];
            a_hi[0] = hh[aoffA + ko];     a_hi[1] = hh[aoffB + ko];
            a_hi[2] = hh[aoffA + ko + 4]; a_hi[3] = hh[aoffB + ko + 4];
            a_lo[0] = hl[aoffA + ko];     a_lo[1] = hl[aoffB + ko];
            a_lo[2] = hl[aoffA + ko + 4]; a_lo[3] = hl[aoffB + ko + 4];
#pragma unroll
            for (int G = 0; G < 4; G++) {
                unsigned b_hi[2], b_lo[2];
                b_hi[0] = Wh[wbase[G] + ko]; b_hi[1] = Wh[wbase[G] + ko + 4];
                b_lo[0] = Wl[wbase[G] + ko]; b_lo[1] = Wl[wbase[G] + ko + 4];
                mma16816(acc[G], a_hi, b_hi);
                mma16816(acc[G], a_hi, b_lo);
                mma16816(acc[G], a_lo, b_hi);
            }
        }

        // ---- LSTM cell update (in-fragment): 4 (row,j) elements ----
        float hnA0, hnA1, hnB0, hnB1;
        {
            float i_, f_, g_, o_, tg;
            i_ = acc[0][0] + xpA[0].x; f_ = acc[1][0] + xpA[1].x;
            g_ = acc[2][0] + xpA[2].x; o_ = acc[3][0] + xpA[3].x;
            tg = tanhf_(g_); cA0 = sigmoidf_(f_) * cA0 + sigmoidf_(i_) * tg; hnA0 = sigmoidf_(o_) * tanhf_(cA0);
            i_ = acc[0][1] + xpA[0].y; f_ = acc[1][1] + xpA[1].y;
            g_ = acc[2][1] + xpA[2].y; o_ = acc[3][1] + xpA[3].y;
            tg = tanhf_(g_); cA1 = sigmoidf_(f_) * cA1 + sigmoidf_(i_) * tg; hnA1 = sigmoidf_(o_) * tanhf_(cA1);
            i_ = acc[0][2] + xpB[0].x; f_ = acc[1][2] + xpB[1].x;
            g_ = acc[2][2] + xpB[2].x; o_ = acc[3][2] + xpB[3].x;
            tg = tanhf_(g_); cB0 = sigmoidf_(f_) * cB0 + sigmoidf_(i_) * tg; hnB0 = sigmoidf_(o_) * tanhf_(cB0);
            i_ = acc[0][3] + xpB[0].y; f_ = acc[1][3] + xpB[1].y;
            g_ = acc[2][3] + xpB[2].y; o_ = acc[3][3] + xpB[3].y;
            tg = tanhf_(g_); cB1 = sigmoidf_(f_) * cB1 + sigmoidf_(i_) * tg; hnB1 = sigmoidf_(o_) * tanhf_(cB1);
        }

        if (ti + 1 < Tt) {
            // ---- stage hn (bf16 hi/lo) into NEXT buffer's own slice ----
            if (stage_ok) {
                __nv_bfloat16 hA0 = __float2bfloat16(hnA0), hA1 = __float2bfloat16(hnA1);
                __nv_bfloat16 hB0 = __float2bfloat16(hnB0), hB1 = __float2bfloat16(hnB1);
                unsigned short s0, s1;
                unsigned uA_hi, uB_hi;
                memcpy(&s0, &hA0, 2); memcpy(&s1, &hA1, 2); uA_hi = (unsigned)s0 | ((unsigned)s1 << 16);
                memcpy(&s0, &hB0, 2); memcpy(&s1, &hB1, 2); uB_hi = (unsigned)s0 | ((unsigned)s1 << 16);
                unsigned uA_lo = pack_bf16x2(hnA0 - __bfloat162float(hA0), hnA1 - __bfloat162float(hA1));
                unsigned uB_lo = pack_bf16x2(hnB0 - __bfloat162float(hB0), hnB1 - __bfloat162float(hB1));
                smu[hnext_base + rA * H_STR + cellA] = uA_hi;
                smu[hnext_base + rB * H_STR + cellA] = uB_hi;
                smu[hnext_base + HHALF + rA * H_STR + cellA] = uA_lo;
                smu[hnext_base + HHALF + rB * H_STR + cellA] = uB_lo;
            }
            __syncthreads();

            // ---- push own slice to 7 peers (float4 per thread) ----
            if (do_push) {
                const unsigned w4 = hnext_base + push_word;
                float4 v = *(const float4*)(smu + w4);
#pragma unroll
                for (int rr = 0; rr < 8; rr++) {
                    if (rr == rank) continue;
                    unsigned* ph = (unsigned*)cluster.map_shared_rank(smu, rr);
                    *(float4*)(ph + w4) = v;
                }
            }

            // ---- aggregated release-arrive on all 8 CTAs' barriers ----
            if (tid == 0) {
                asm volatile("fence.acq_rel.cluster;" ::: "memory");
                const uint32_t mb = buf ? mbar_addr0 : mbar_addr1;
#pragma unroll
                for (int rr = 0; rr < 8; rr++) mbar_arrive_rank(mb, rr);
            }
        }

        // ---- write h to global for the output stage ----
        if (jvalid) {
            size_t baseA = ((size_t)(dir * Bb + b0 + rA) * Tt + tcur) * Hh + jg;
            size_t baseB = ((size_t)(dir * Bb + b0 + rB) * Tt + tcur) * Hh + jg;
            *(float2*)(g_h + baseA) = make_float2(hnA0, hnA1);
            *(float2*)(g_h + baseB) = make_float2(hnB0, hnB1);
        }

#pragma unroll
        for (int G = 0; G < 4; G++) { xpA[G] = xpnA[G]; xpB[G] = xpnB[G]; }
    }
}

// =================================================================
// K3: output linear + softmax. One warp per (b,t). (unchanged)
// =================================================================
__global__ void out_kernel(const float* __restrict__ W_lin,
                           const float* __restrict__ b_lin,
                           float* __restrict__ out) {
    const int warp = (blockIdx.x * blockDim.x + threadIdx.x) >> 5;
    const int lane = threadIdx.x & 31;
    if (warp >= Bb * Tt) return;
    const int b = warp / Tt;
    const int t = warp % Tt;

    const float* hf = g_h + ((size_t)(0 * Bb + b) * Tt + t) * Hh;
    const float* hb = g_h + ((size_t)(1 * Bb + b) * Tt + t) * Hh;

    float acc[Oo];
#pragma unroll
    for (int o = 0; o < Oo; o++) acc[o] = 0.f;

    for (int k = lane; k < Hh; k += 32) {
        float a = hf[k];
        float c = hb[k];
#pragma unroll
        for (int o = 0; o < Oo; o++)
            acc[o] += a * W_lin[o * (2 * Hh) + k] + c * W_lin[o * (2 * Hh) + Hh + k];
    }
#pragma unroll
    for (int o = 0; o < Oo; o++) {
#pragma unroll
        for (int off = 16; off > 0; off >>= 1)
            acc[o] += __shfl_xor_sync(0xFFFFFFFFu, acc[o], off);
        acc[o] += b_lin[o];
    }
    float mx = acc[0];
#pragma unroll
    for (int o = 1; o < Oo; o++) mx = fmaxf(mx, acc[o]);
    float s = 0.f;
    float e[Oo];
#pragma unroll
    for (int o = 0; o < Oo; o++) { e[o] = __expf(acc[o] - mx); s += e[o]; }
    float inv = 1.0f / s;
    if (lane < Oo) out[(size_t)warp * Oo + lane] = e[lane] * inv;
}

// =================================================================
// launcher
// =================================================================
extern "C" void kernel_launch(void* const* d_in, const int* in_sizes, int n_in,
                              void* d_out, int out_size) {
    const int*   x     = (const int*)  d_in[0];
    const float* emb   = (const float*)d_in[1];
    const float* Wih_f = (const float*)d_in[2];
    const float* Whh_f = (const float*)d_in[3];
    const float* b_f   = (const float*)d_in[4];
    const float* Wih_b = (const float*)d_in[5];
    const float* Whh_b = (const float*)d_in[6];
    const float* b_b   = (const float*)d_in[7];
    const float* W_lin = (const float*)d_in[8];
    const float* b_lin = (const float*)d_in[9];
    float* out = (float*)d_out;

    cudaFuncSetAttribute(lstm_rec_kernel,
                         cudaFuncAttributeMaxDynamicSharedMemorySize, REC_SMEM);

    static unsigned *p_emb_hi = nullptr, *p_emb_lo = nullptr, *p_wih_hi = nullptr, *p_wih_lo = nullptr;
    if (!p_emb_hi) {
        cudaGetSymbolAddress((void**)&p_emb_hi, g_emb_hi);
        cudaGetSymbolAddress((void**)&p_emb_lo, g_emb_lo);
        cudaGetSymbolAddress((void**)&p_wih_hi, g_wih_hi);
        cudaGetSymbolAddress((void**)&p_wih_lo, g_wih_lo);
    }

    // K0: hi/lo splits (proj inputs)
    {
        size_t cells = (size_t)Vv * KC;
        split_kernel<<<(unsigned)((cells + 255) / 256), 256>>>(emb, p_emb_hi, p_emb_lo, Vv);
        size_t wc = (size_t)G4 * KC;
        split_kernel<<<(unsigned)((wc + 255) / 256), 256>>>(Wih_f, p_wih_hi, p_wih_lo, G4);
        split_kernel<<<(unsigned)((wc + 255) / 256), 256>>>(Wih_b, p_wih_hi + wc, p_wih_lo + wc, G4);
    }

    // K1: proj via mma.sync bf16. grid = (15 n-tiles, 250 m-tiles, 2 dirs)
    {
        dim3 grid(G4 / PJ_BN, Vv / PJ_BM, 2);
        proj_mma_kernel<<<grid, 256>>>(b_f, b_b);
    }

    // K2: recurrence (MMA). 128 CTAs, clusters of 8, 160 threads.
    lstm_rec_kernel<<<128, REC_THREADS, REC_SMEM>>>(x, Whh_f, Whh_b);

    // K3: output. 65536 warps.
    {
        int warps_per_block = 8;
        int blocks = (Bb * Tt) / warps_per_block;
        out_kernel<<<blocks, warps_per_block * 32>>>(W_lin, b_lin, out);
    }
}